// round 12
// baseline (speedup 1.0000x reference)
#include <cuda_runtime.h>
#include <cuda_fp16.h>
#include <math.h>
#include <stdint.h>

// ---------------------------------------------------------------------------
// Problem constants
// ---------------------------------------------------------------------------
#define BD      2
#define LSEQ    2048
#define DMODEL  2048
#define NH      16
#define HD      128
#define ROWS    (BD * LSEQ)      // 4096

// ---------------------------------------------------------------------------
// Scratch (device globals -- no allocation allowed)
// ---------------------------------------------------------------------------
__device__ float g_qkv[ROWS * 3 * DMODEL];                 // fp32
__device__ float g_x2 [ROWS * DMODEL];
__device__ float g_p  [(size_t)ROWS * 8 * DMODEL];

__device__ __half g_xn [ROWS * DMODEL];
__device__ __half g_o  [ROWS * DMODEL];
__device__ __half g_ff [(size_t)ROWS * 4 * DMODEL];
// transposed weights [N, K] fp16
__device__ __half g_wqkv[3 * DMODEL * DMODEL];
__device__ __half g_wo  [DMODEL * DMODEL];
__device__ __half g_wp  [(size_t)8 * DMODEL * DMODEL];
__device__ __half g_wff [(size_t)4 * DMODEL * DMODEL];

// ---------------------------------------------------------------------------
// Helpers
// ---------------------------------------------------------------------------
__device__ __forceinline__ uint32_t smem_u32(const void* p) {
    uint32_t a;
    asm("{ .reg .u64 t; cvta.to.shared.u64 t, %1; cvt.u32.u64 %0, t; }"
        : "=r"(a) : "l"(p));
    return a;
}
__device__ __forceinline__ void cp16(uint32_t dst, const void* src) {
    asm volatile("cp.async.cg.shared.global [%0], [%1], 16;" :: "r"(dst), "l"(src));
}
__device__ __forceinline__ void ldsm_x4(uint32_t* r, uint32_t a) {
    asm volatile("ldmatrix.sync.aligned.m8n8.x4.shared.b16 {%0,%1,%2,%3}, [%4];"
        : "=r"(r[0]), "=r"(r[1]), "=r"(r[2]), "=r"(r[3]) : "r"(a));
}
__device__ __forceinline__ void ldsm_x2(uint32_t* r, uint32_t a) {
    asm volatile("ldmatrix.sync.aligned.m8n8.x2.shared.b16 {%0,%1}, [%2];"
        : "=r"(r[0]), "=r"(r[1]) : "r"(a));
}
__device__ __forceinline__ void mma_f32(float* d, const uint32_t* a, const uint32_t* b) {
    asm volatile("mma.sync.aligned.m16n8k16.row.col.f32.f16.f16.f32 "
        "{%0,%1,%2,%3}, {%4,%5,%6,%7}, {%8,%9}, {%0,%1,%2,%3};"
        : "+f"(d[0]), "+f"(d[1]), "+f"(d[2]), "+f"(d[3])
        : "r"(a[0]), "r"(a[1]), "r"(a[2]), "r"(a[3]), "r"(b[0]), "r"(b[1]));
}

// ---------------------------------------------------------------------------
// fp16 mma GEMM (single pass): C[M,N] = A[M,K] @ B[N,K]^T + bias (+res)
// fp32 accumulation. CTA 128x256, 16 warps (4x4), warp tile 32x64,
// 512 threads (4 warps/SMSP). K-chunk 32, 4-stage cp.async (120KB smem),
// one syncthreads per chunk. Pitch 40 fp16 (80B): ldmatrix conflict-free.
// ---------------------------------------------------------------------------
#define GK       32
#define APITCH_B 80
#define COMP_A   10240            // 128 rows * 80B (A region size)
#define COMP_B2  20480            // 256 rows * 80B (B region size)
#define STAGE_B  30720            // A + B
#define NSTAGE   4
#define GSMEM    (NSTAGE * STAGE_B)   // 122880

__device__ __forceinline__ void g_load_chunk(
    uint32_t st, int c, int tid,
    const __half* __restrict__ A, const __half* __restrict__ B,
    int K, int m0, int n0)
{
    const int k0 = c * GK;
    // 512 threads x 3 iters = 1536 cp16: 384 rows x 4 chunks (A 128 + B 256)
    #pragma unroll
    for (int i = 0; i < 3; i++) {
        int e = tid + (i << 9);
        int r = e >> 2, cc = e & 3;
        if (r < 128) {
            cp16(st + (uint32_t)(r * APITCH_B + cc * 16),
                 A + (size_t)(m0 + r) * K + k0 + cc * 8);
        } else {
            int rb = r - 128;
            cp16(st + (uint32_t)(COMP_A + rb * APITCH_B + cc * 16),
                 B + (size_t)(n0 + rb) * K + k0 + cc * 8);
        }
    }
    asm volatile("cp.async.commit_group;" ::: "memory");
}

__global__ void __launch_bounds__(512)
gemm_kernel(const __half* __restrict__ A, const __half* __restrict__ B,
            const float* __restrict__ bias, const float* __restrict__ res,
            float* __restrict__ C, int K, int N)
{
    extern __shared__ __align__(16) char sm_[];
    const uint32_t sb = smem_u32(sm_);
    const int tid  = threadIdx.x;
    const int lane = tid & 31;
    const int wid  = tid >> 5;          // 0..15
    const int wm   = wid >> 2;          // 0..3  (m offset wm*32)
    const int wn   = wid & 3;           // 0..3  (n offset wn*64)
    const int m0 = blockIdx.y << 7;
    const int n0 = blockIdx.x << 8;     // 256-wide N tile
    const int NC = K / GK;

    float acc[2][8][4];
    #pragma unroll
    for (int i = 0; i < 2; i++)
        #pragma unroll
        for (int j = 0; j < 8; j++)
            #pragma unroll
            for (int q = 0; q < 4; q++) acc[i][j][q] = 0.f;

    g_load_chunk(sb,               0, tid, A, B, K, m0, n0);
    g_load_chunk(sb + STAGE_B,     1, tid, A, B, K, m0, n0);
    g_load_chunk(sb + 2 * STAGE_B, 2, tid, A, B, K, m0, n0);

    // ldmatrix per-lane source offsets (bytes)
    const int rowA  = (lane & 7) + ((lane >> 3) & 1) * 8;
    const int kaddA = (lane >> 4) * 16;
    const uint32_t a_ld = (uint32_t)((wm * 32 + rowA) * APITCH_B + kaddA);
    const int rowB  = lane & 7;
    const int kaddB = ((lane >> 3) & 1) * 16;
    const uint32_t b_ld = (uint32_t)(COMP_A + (wn * 64 + rowB) * APITCH_B + kaddB);

    for (int c = 0; c < NC; c++) {
        asm volatile("cp.async.wait_group 2;" ::: "memory");
        __syncthreads();

        if (c + 3 < NC)
            g_load_chunk(sb + (uint32_t)((c + 3) & 3) * STAGE_B, c + 3, tid,
                         A, B, K, m0, n0);

        const uint32_t st = sb + (uint32_t)(c & 3) * STAGE_B;

        #pragma unroll
        for (int kh = 0; kh < 2; kh++) {
            const uint32_t abase = st + a_ld + kh * 32;
            const uint32_t bbase = st + b_ld + kh * 32;

            uint32_t ar[2][4], br[8][2];
            #pragma unroll
            for (int mt = 0; mt < 2; mt++)
                ldsm_x4(ar[mt], abase + mt * (16 * APITCH_B));
            #pragma unroll
            for (int nt = 0; nt < 8; nt++)
                ldsm_x2(br[nt], bbase + nt * (8 * APITCH_B));

            #pragma unroll
            for (int mt = 0; mt < 2; mt++)
                #pragma unroll
                for (int nt = 0; nt < 8; nt++)
                    mma_f32(acc[mt][nt], ar[mt], br[nt]);
        }
    }

    // epilogue
    #pragma unroll
    for (int mt = 0; mt < 2; mt++) {
        #pragma unroll
        for (int nt = 0; nt < 8; nt++) {
            const int rg = m0 + wm * 32 + mt * 16 + (lane >> 2);
            const int cg = n0 + wn * 64 + nt * 8 + (lane & 3) * 2;
            float2 bv = *(const float2*)(bias + cg);
            float2 o0, o1;
            o0.x = acc[mt][nt][0] + bv.x;  o0.y = acc[mt][nt][1] + bv.y;
            o1.x = acc[mt][nt][2] + bv.x;  o1.y = acc[mt][nt][3] + bv.y;
            if (res) {
                float2 r0 = *(const float2*)(res + (size_t)rg * N + cg);
                float2 r1 = *(const float2*)(res + (size_t)(rg + 8) * N + cg);
                o0.x += r0.x; o0.y += r0.y;
                o1.x += r1.x; o1.y += r1.y;
            }
            *(float2*)(C + (size_t)rg * N + cg)       = o0;
            *(float2*)(C + (size_t)(rg + 8) * N + cg) = o1;
        }
    }
}

// ---------------------------------------------------------------------------
// Weight transpose + fp16 round: W[K,N] fp32 -> Th[N,K] fp16
// ---------------------------------------------------------------------------
__global__ void __launch_bounds__(256)
transp_half(const float* __restrict__ W, __half* __restrict__ Th, int Kd, int Nd)
{
    __shared__ float t[32][33];
    const int n0 = blockIdx.x * 32, k0 = blockIdx.y * 32;
    const int tx = threadIdx.x & 31, ty = threadIdx.x >> 5;
    #pragma unroll
    for (int i = 0; i < 4; i++) {
        int kk = ty + i * 8;
        t[kk][tx] = W[(size_t)(k0 + kk) * Nd + n0 + tx];
    }
    __syncthreads();
    #pragma unroll
    for (int i = 0; i < 4; i++) {
        int nn = ty + i * 8;
        Th[(size_t)(n0 + nn) * Kd + k0 + tx] = __float2half_rn(t[tx][nn]);
    }
}

// ---------------------------------------------------------------------------
// RMSNorm -> fp16
// ---------------------------------------------------------------------------
__global__ void __launch_bounds__(256)
rmsnorm_half(const float* __restrict__ in, const float* __restrict__ g,
             __half* __restrict__ outh)
{
    __shared__ float red[8];
    const int row = blockIdx.x;
    const int tid = threadIdx.x;
    const float4* inr = (const float4*)(in + (size_t)row * DMODEL);
    float4 v0 = inr[tid];
    float4 v1 = inr[tid + 256];
    float ss = v0.x*v0.x + v0.y*v0.y + v0.z*v0.z + v0.w*v0.w
             + v1.x*v1.x + v1.y*v1.y + v1.z*v1.z + v1.w*v1.w;
    #pragma unroll
    for (int o = 16; o; o >>= 1) ss += __shfl_xor_sync(0xffffffffu, ss, o);
    if ((tid & 31) == 0) red[tid >> 5] = ss;
    __syncthreads();
    float tot = red[0]+red[1]+red[2]+red[3]+red[4]+red[5]+red[6]+red[7];
    float rs = rsqrtf(tot * (1.0f / DMODEL) + 1e-8f);

    const float4* gr = (const float4*)g;
    float4 ga = gr[tid], gb = gr[tid + 256];
    __half2* oh2 = (__half2*)(outh + (size_t)row * DMODEL);
    float y[8] = { v0.x*rs*ga.x, v0.y*rs*ga.y, v0.z*rs*ga.z, v0.w*rs*ga.w,
                   v1.x*rs*gb.x, v1.y*rs*gb.y, v1.z*rs*gb.z, v1.w*rs*gb.w };
    #pragma unroll
    for (int p = 0; p < 4; p++) {
        __half2 hh;
        hh.x = __float2half_rn(y[p*2]);
        hh.y = __float2half_rn(y[p*2+1]);
        int base = (p < 2) ? (tid*2 + p) : ((tid+256)*2 + (p-2));
        oh2[base] = hh;
    }
}

// ---------------------------------------------------------------------------
// RoPE (in place on q,k of qkv)
// ---------------------------------------------------------------------------
__global__ void __launch_bounds__(256)
rope_kernel(float* __restrict__ qkv)
{
    const long idx = (long)blockIdx.x * 256 + threadIdx.x;
    const int  i   = (int)(idx & 63);
    const int  h   = (int)((idx >> 6) & 15);
    const long bl  = idx >> 10;
    const long l   = bl & 2047;

    float freq = expf(-(float)i * 0.14391156642875464f);
    float angle = (float)l * freq;
    float s, c;
    sincosf(angle, &s, &c);

    float* qp = qkv + bl * (3 * DMODEL) + h * HD + i;
    float* kp = qp + DMODEL;
    float q1 = qp[0], q2 = qp[64];
    float k1 = kp[0], k2 = kp[64];
    qp[0]  = q1 * c - q2 * s;
    qp[64] = q2 * c + q1 * s;
    kp[0]  = k1 * c - k2 * s;
    kp[64] = k2 * c + k1 * s;
}

// ---------------------------------------------------------------------------
// Flash attention (causal, fp32), outputs fp16
// ---------------------------------------------------------------------------
#define ATT_BM   64
#define ATT_BN   64
#define QSTRIDE  132
#define PSTRIDE  68
#define ATT_SMEM ((3 * ATT_BM * QSTRIDE + ATT_BM * PSTRIDE) * (int)sizeof(float))

__global__ void __launch_bounds__(256)
attn_kernel(const float* __restrict__ qkv, __half* __restrict__ Oh)
{
    extern __shared__ float smem[];
    float* sQ = smem;
    float* sK = sQ + ATT_BM * QSTRIDE;
    float* sV = sK + ATT_BN * QSTRIDE;
    float* sP = sV + ATT_BN * QSTRIDE;

    const int bh = blockIdx.y;
    const int b  = bh >> 4;
    const int h  = bh & 15;
    const int qi = gridDim.x - 1 - blockIdx.x;
    const int q0 = qi * ATT_BM;
    const int tid = threadIdx.x;
    const int r  = tid >> 2;
    const int qd = tid & 3;

    const float* qbase = qkv + (size_t)(b * LSEQ) * (3 * DMODEL) + h * HD;
    const float* kbase = qbase + DMODEL;
    const float* vbase = qbase + 2 * DMODEL;

    for (int i = tid; i < ATT_BM * 32; i += 256) {
        int row = i >> 5, c4 = (i & 31) << 2;
        *(float4*)(sQ + row * QSTRIDE + c4) =
            *(const float4*)(qbase + (size_t)(q0 + row) * (3 * DMODEL) + c4);
    }

    float accO[32];
    #pragma unroll
    for (int i = 0; i < 32; i++) accO[i] = 0.f;
    float mrow = -1e30f, lrow = 0.f;
    const int qg = q0 + r;
    const float scale = 0.088388347648318447f;

    const int nk = qi + 1;
    for (int kt = 0; kt < nk; kt++) {
        const int k0 = kt * ATT_BN;
        __syncthreads();
        for (int i = tid; i < ATT_BN * 32; i += 256) {
            int row = i >> 5, c4 = (i & 31) << 2;
            size_t goff = (size_t)(k0 + row) * (3 * DMODEL) + c4;
            *(float4*)(sK + row * QSTRIDE + c4) = *(const float4*)(kbase + goff);
            *(float4*)(sV + row * QSTRIDE + c4) = *(const float4*)(vbase + goff);
        }
        __syncthreads();

        float s[16];
        #pragma unroll
        for (int jj = 0; jj < 16; jj++) s[jj] = 0.f;
        const float* qr = sQ + r * QSTRIDE;
        #pragma unroll 2
        for (int d = 0; d < HD; d += 4) {
            float4 qv = *(const float4*)(qr + d);
            #pragma unroll
            for (int jj = 0; jj < 16; jj++) {
                float4 kv = *(const float4*)(sK + (qd + (jj << 2)) * QSTRIDE + d);
                s[jj] = fmaf(qv.x, kv.x, s[jj]);
                s[jj] = fmaf(qv.y, kv.y, s[jj]);
                s[jj] = fmaf(qv.z, kv.z, s[jj]);
                s[jj] = fmaf(qv.w, kv.w, s[jj]);
            }
        }

        float tmax = -1e30f;
        #pragma unroll
        for (int jj = 0; jj < 16; jj++) {
            int jgl = k0 + qd + (jj << 2);
            s[jj] = (jgl <= qg) ? s[jj] * scale : -1e30f;
            tmax = fmaxf(tmax, s[jj]);
        }
        tmax = fmaxf(tmax, __shfl_xor_sync(0xffffffffu, tmax, 1));
        tmax = fmaxf(tmax, __shfl_xor_sync(0xffffffffu, tmax, 2));

        float mnew = fmaxf(mrow, tmax);
        float corr = __expf(mrow - mnew);
        float psum = 0.f;
        #pragma unroll
        for (int jj = 0; jj < 16; jj++) {
            float p = __expf(s[jj] - mnew);
            s[jj] = p;
            psum += p;
        }
        psum += __shfl_xor_sync(0xffffffffu, psum, 1);
        psum += __shfl_xor_sync(0xffffffffu, psum, 2);
        lrow = lrow * corr + psum;
        mrow = mnew;
        #pragma unroll
        for (int i = 0; i < 32; i++) accO[i] *= corr;

        #pragma unroll
        for (int jj = 0; jj < 16; jj++)
            sP[r * PSTRIDE + qd + (jj << 2)] = s[jj];
        __syncthreads();

        const float* prow = sP + r * PSTRIDE;
        #pragma unroll 4
        for (int j = 0; j < ATT_BN; j++) {
            float p = prow[j];
            const float4* vr = (const float4*)(sV + j * QSTRIDE + (qd << 5));
            #pragma unroll
            for (int cc = 0; cc < 8; cc++) {
                float4 vv = vr[cc];
                accO[cc * 4 + 0] = fmaf(p, vv.x, accO[cc * 4 + 0]);
                accO[cc * 4 + 1] = fmaf(p, vv.y, accO[cc * 4 + 1]);
                accO[cc * 4 + 2] = fmaf(p, vv.z, accO[cc * 4 + 2]);
                accO[cc * 4 + 3] = fmaf(p, vv.w, accO[cc * 4 + 3]);
            }
        }
    }

    float inv = 1.f / lrow;
    size_t base = (size_t)(b * LSEQ + qg) * DMODEL + h * HD + (qd << 5);
    __half2* oh2 = (__half2*)(Oh + base);
    #pragma unroll
    for (int cc = 0; cc < 16; cc++) {
        __half2 hh;
        hh.x = __float2half_rn(accO[cc * 2] * inv);
        hh.y = __float2half_rn(accO[cc * 2 + 1] * inv);
        oh2[cc] = hh;
    }
}

// ---------------------------------------------------------------------------
// SwiGLU -> fp16  (per-float4 of the OUTPUT: ROWS*4*DMODEL elements)
// ---------------------------------------------------------------------------
__global__ void __launch_bounds__(256)
swiglu_half(const float* __restrict__ P, __half* __restrict__ Fh)
{
    size_t i4 = (size_t)blockIdx.x * 256 + threadIdx.x;  // output float4 index
    if (i4 >= (size_t)ROWS * 4 * DMODEL / 4) return;
    size_t rr  = i4 >> 11;       // 2048 float4 per 8192-wide output row
    size_t kk4 = i4 & 2047;
    const float4 gt = *(const float4*)(P + rr * 16384 + kk4 * 4);
    const float4 vl = *(const float4*)(P + rr * 16384 + 8192 + kk4 * 4);
    float f[4];
    f[0] = gt.x / (1.f + __expf(-gt.x)) * vl.x;
    f[1] = gt.y / (1.f + __expf(-gt.y)) * vl.y;
    f[2] = gt.z / (1.f + __expf(-gt.z)) * vl.z;
    f[3] = gt.w / (1.f + __expf(-gt.w)) * vl.w;
    size_t ob = rr * 8192 + kk4 * 4;
    __half2* fh2 = (__half2*)(Fh + ob);
    #pragma unroll
    for (int p = 0; p < 2; p++) {
        __half2 hh;
        hh.x = __float2half_rn(f[p*2]);
        hh.y = __float2half_rn(f[p*2+1]);
        fh2[p] = hh;
    }
}

// ---------------------------------------------------------------------------
// Host launcher
// ---------------------------------------------------------------------------
extern "C" void kernel_launch(void* const* d_in, const int* in_sizes, int n_in,
                              void* d_out, int out_size)
{
    const float* x    = (const float*)d_in[0];
    const float* Wqkv = (const float*)d_in[1];
    const float* bqkv = (const float*)d_in[2];
    const float* Wo   = (const float*)d_in[3];
    const float* bo   = (const float*)d_in[4];
    const float* g1   = (const float*)d_in[5];
    const float* g2   = (const float*)d_in[6];
    const float* Wp   = (const float*)d_in[7];
    const float* bp   = (const float*)d_in[8];
    const float* Wff  = (const float*)d_in[9];
    const float* bff  = (const float*)d_in[10];
    float* out = (float*)d_out;

    float *p_qkv, *p_x2, *p_p;
    __half *p_xn, *p_o, *p_ff;
    __half *p_wqkv, *p_wo, *p_wp, *p_wff;
    cudaGetSymbolAddress((void**)&p_qkv, g_qkv);
    cudaGetSymbolAddress((void**)&p_x2,  g_x2);
    cudaGetSymbolAddress((void**)&p_p,   g_p);
    cudaGetSymbolAddress((void**)&p_xn,  g_xn);
    cudaGetSymbolAddress((void**)&p_o,   g_o);
    cudaGetSymbolAddress((void**)&p_ff,  g_ff);
    cudaGetSymbolAddress((void**)&p_wqkv, g_wqkv);
    cudaGetSymbolAddress((void**)&p_wo,   g_wo);
    cudaGetSymbolAddress((void**)&p_wp,   g_wp);
    cudaGetSymbolAddress((void**)&p_wff,  g_wff);

    cudaFuncSetAttribute(attn_kernel, cudaFuncAttributeMaxDynamicSharedMemorySize, ATT_SMEM);
    cudaFuncSetAttribute(gemm_kernel, cudaFuncAttributeMaxDynamicSharedMemorySize, GSMEM);

    // Weight transposition (fp16)
    transp_half<<<dim3(3 * DMODEL / 32, DMODEL / 32), 256>>>(Wqkv, p_wqkv, DMODEL, 3 * DMODEL);
    transp_half<<<dim3(DMODEL / 32, DMODEL / 32), 256>>>(Wo, p_wo, DMODEL, DMODEL);
    transp_half<<<dim3(8 * DMODEL / 32, DMODEL / 32), 256>>>(Wp, p_wp, DMODEL, 8 * DMODEL);
    transp_half<<<dim3(DMODEL / 32, 4 * DMODEL / 32), 256>>>(Wff, p_wff, 4 * DMODEL, DMODEL);

    // 1. pre-norm (-> fp16)
    rmsnorm_half<<<ROWS, 256>>>(x, g1, p_xn);

    // 2. QKV projection
    gemm_kernel<<<dim3(3 * DMODEL / 256, ROWS / 128), 512, GSMEM>>>(
        p_xn, p_wqkv, bqkv, nullptr, p_qkv, DMODEL, 3 * DMODEL);

    // 3. RoPE
    rope_kernel<<<(ROWS * NH * 64) / 256, 256>>>(p_qkv);

    // 4. causal flash attention (-> fp16)
    attn_kernel<<<dim3(LSEQ / ATT_BM, BD * NH), 256, ATT_SMEM>>>(p_qkv, p_o);

    // 5. output projection + residual
    gemm_kernel<<<dim3(DMODEL / 256, ROWS / 128), 512, GSMEM>>>(
        p_o, p_wo, bo, x, p_x2, DMODEL, DMODEL);

    // 6. second pre-norm (-> fp16)
    rmsnorm_half<<<ROWS, 256>>>(p_x2, g2, p_xn);

    // 7. FFN up-projection
    gemm_kernel<<<dim3(8 * DMODEL / 256, ROWS / 128), 512, GSMEM>>>(
        p_xn, p_wp, bp, nullptr, p_p, DMODEL, 8 * DMODEL);

    // 8. SwiGLU (-> fp16)
    swiglu_half<<<(ROWS * 4 * DMODEL / 4) / 256, 256>>>(p_p, p_ff);

    // 9. FFN down-projection + residual -> output
    gemm_kernel<<<dim3(DMODEL / 256, ROWS / 128), 512, GSMEM>>>(
        p_ff, p_wff, bff, p_x2, out, 4 * DMODEL, DMODEL);
}

// round 13
// speedup vs baseline: 3.1390x; 3.1390x over previous
#include <cuda_runtime.h>
#include <cuda_fp16.h>
#include <math.h>
#include <stdint.h>

// ---------------------------------------------------------------------------
// Problem constants
// ---------------------------------------------------------------------------
#define BD      2
#define LSEQ    2048
#define DMODEL  2048
#define NH      16
#define HD      128
#define ROWS    (BD * LSEQ)      // 4096

// ---------------------------------------------------------------------------
// Scratch (device globals -- no allocation allowed)
// ---------------------------------------------------------------------------
__device__ float g_qkv[ROWS * 3 * DMODEL];                 // fp32
__device__ float g_x2 [ROWS * DMODEL];
__device__ float g_p  [(size_t)ROWS * 8 * DMODEL];

__device__ __half g_xn [ROWS * DMODEL];
__device__ __half g_o  [ROWS * DMODEL];
__device__ __half g_ff [(size_t)ROWS * 4 * DMODEL];
__device__ __half g_qf [ROWS * DMODEL];   // [bh][L][HD], q pre-scaled + roped
__device__ __half g_kf [ROWS * DMODEL];   // [bh][L][HD], roped
__device__ __half g_vf [ROWS * DMODEL];   // [bh][L][HD]
// transposed weights [N, K] fp16
__device__ __half g_wqkv[3 * DMODEL * DMODEL];
__device__ __half g_wo  [DMODEL * DMODEL];
__device__ __half g_wp  [(size_t)8 * DMODEL * DMODEL];
__device__ __half g_wff [(size_t)4 * DMODEL * DMODEL];

// ---------------------------------------------------------------------------
// Helpers
// ---------------------------------------------------------------------------
__device__ __forceinline__ uint32_t smem_u32(const void* p) {
    uint32_t a;
    asm("{ .reg .u64 t; cvta.to.shared.u64 t, %1; cvt.u32.u64 %0, t; }"
        : "=r"(a) : "l"(p));
    return a;
}
__device__ __forceinline__ void cp16(uint32_t dst, const void* src) {
    asm volatile("cp.async.cg.shared.global [%0], [%1], 16;" :: "r"(dst), "l"(src));
}
__device__ __forceinline__ void ldsm_x4(uint32_t* r, uint32_t a) {
    asm volatile("ldmatrix.sync.aligned.m8n8.x4.shared.b16 {%0,%1,%2,%3}, [%4];"
        : "=r"(r[0]), "=r"(r[1]), "=r"(r[2]), "=r"(r[3]) : "r"(a));
}
__device__ __forceinline__ void ldsm_x2(uint32_t* r, uint32_t a) {
    asm volatile("ldmatrix.sync.aligned.m8n8.x2.shared.b16 {%0,%1}, [%2];"
        : "=r"(r[0]), "=r"(r[1]) : "r"(a));
}
__device__ __forceinline__ void ldsm_x2t(uint32_t* r, uint32_t a) {
    asm volatile("ldmatrix.sync.aligned.m8n8.x2.trans.shared.b16 {%0,%1}, [%2];"
        : "=r"(r[0]), "=r"(r[1]) : "r"(a));
}
__device__ __forceinline__ void mma_f32(float* d, const uint32_t* a, const uint32_t* b) {
    asm volatile("mma.sync.aligned.m16n8k16.row.col.f32.f16.f16.f32 "
        "{%0,%1,%2,%3}, {%4,%5,%6,%7}, {%8,%9}, {%0,%1,%2,%3};"
        : "+f"(d[0]), "+f"(d[1]), "+f"(d[2]), "+f"(d[3])
        : "r"(a[0]), "r"(a[1]), "r"(a[2]), "r"(a[3]), "r"(b[0]), "r"(b[1]));
}
__device__ __forceinline__ uint32_t pack2h(float a, float b) {
    __half2 h = __floats2half2_rn(a, b);
    return *(uint32_t*)&h;
}

// ---------------------------------------------------------------------------
// fp16 mma GEMM (from R11 best): C[M,N] = A[M,K] @ B[N,K]^T + bias (+res)
// CTA 128x128, 16 warps, warp tile 32x32, 512 threads, K-chunk 32,
// 4-stage cp.async (80KB smem). Pitch 80B: ldmatrix conflict-free.
// ---------------------------------------------------------------------------
#define GK       32
#define APITCH_B 80
#define COMP_B   10240
#define STAGE_B  20480
#define NSTAGE   4
#define GSMEM    (NSTAGE * STAGE_B)   // 81920

__device__ __forceinline__ void g_load_chunk(
    uint32_t st, int c, int tid,
    const __half* __restrict__ A, const __half* __restrict__ B,
    int K, int m0, int n0)
{
    const int k0 = c * GK;
    int r = tid >> 2, cc = tid & 3;
    uint32_t so = (uint32_t)(r * APITCH_B + cc * 16);
    cp16(st + so,          A + (size_t)(m0 + r) * K + k0 + cc * 8);
    cp16(st + COMP_B + so, B + (size_t)(n0 + r) * K + k0 + cc * 8);
    asm volatile("cp.async.commit_group;" ::: "memory");
}

__global__ void __launch_bounds__(512)
gemm_kernel(const __half* __restrict__ A, const __half* __restrict__ B,
            const float* __restrict__ bias, const float* __restrict__ res,
            float* __restrict__ C, int K, int N)
{
    extern __shared__ __align__(16) char sm_[];
    const uint32_t sb = smem_u32(sm_);
    const int tid  = threadIdx.x;
    const int lane = tid & 31;
    const int wid  = tid >> 5;
    const int wm   = wid >> 2;
    const int wn   = wid & 3;
    const int m0 = blockIdx.y << 7;
    const int n0 = blockIdx.x << 7;
    const int NC = K / GK;

    float acc[2][4][4];
    #pragma unroll
    for (int i = 0; i < 2; i++)
        #pragma unroll
        for (int j = 0; j < 4; j++)
            #pragma unroll
            for (int q = 0; q < 4; q++) acc[i][j][q] = 0.f;

    g_load_chunk(sb,               0, tid, A, B, K, m0, n0);
    g_load_chunk(sb + STAGE_B,     1, tid, A, B, K, m0, n0);
    g_load_chunk(sb + 2 * STAGE_B, 2, tid, A, B, K, m0, n0);

    const int rowA  = (lane & 7) + ((lane >> 3) & 1) * 8;
    const int kaddA = (lane >> 4) * 16;
    const uint32_t a_ld = (uint32_t)((wm * 32 + rowA) * APITCH_B + kaddA);
    const int rowB  = lane & 7;
    const int kaddB = ((lane >> 3) & 1) * 16;
    const uint32_t b_ld = (uint32_t)((wn * 32 + rowB) * APITCH_B + kaddB);

    for (int c = 0; c < NC; c++) {
        asm volatile("cp.async.wait_group 2;" ::: "memory");
        __syncthreads();

        if (c + 3 < NC)
            g_load_chunk(sb + (uint32_t)((c + 3) & 3) * STAGE_B, c + 3, tid,
                         A, B, K, m0, n0);

        const uint32_t st = sb + (uint32_t)(c & 3) * STAGE_B;

        #pragma unroll
        for (int kh = 0; kh < 2; kh++) {
            const uint32_t abase = st + a_ld + kh * 32;
            const uint32_t bbase = st + COMP_B + b_ld + kh * 32;

            uint32_t ar[2][4], br[4][2];
            #pragma unroll
            for (int mt = 0; mt < 2; mt++)
                ldsm_x4(ar[mt], abase + mt * (16 * APITCH_B));
            #pragma unroll
            for (int nt = 0; nt < 4; nt++)
                ldsm_x2(br[nt], bbase + nt * (8 * APITCH_B));

            #pragma unroll
            for (int mt = 0; mt < 2; mt++)
                #pragma unroll
                for (int nt = 0; nt < 4; nt++)
                    mma_f32(acc[mt][nt], ar[mt], br[nt]);
        }
    }

    #pragma unroll
    for (int mt = 0; mt < 2; mt++) {
        #pragma unroll
        for (int nt = 0; nt < 4; nt++) {
            const int rg = m0 + wm * 32 + mt * 16 + (lane >> 2);
            const int cg = n0 + wn * 32 + nt * 8 + (lane & 3) * 2;
            float2 bv = *(const float2*)(bias + cg);
            float2 o0, o1;
            o0.x = acc[mt][nt][0] + bv.x;  o0.y = acc[mt][nt][1] + bv.y;
            o1.x = acc[mt][nt][2] + bv.x;  o1.y = acc[mt][nt][3] + bv.y;
            if (res) {
                float2 r0 = *(const float2*)(res + (size_t)rg * N + cg);
                float2 r1 = *(const float2*)(res + (size_t)(rg + 8) * N + cg);
                o0.x += r0.x; o0.y += r0.y;
                o1.x += r1.x; o1.y += r1.y;
            }
            *(float2*)(C + (size_t)rg * N + cg)       = o0;
            *(float2*)(C + (size_t)(rg + 8) * N + cg) = o1;
        }
    }
}

// ---------------------------------------------------------------------------
// Weight transpose + fp16 round
// ---------------------------------------------------------------------------
__global__ void __launch_bounds__(256)
transp_half(const float* __restrict__ W, __half* __restrict__ Th, int Kd, int Nd)
{
    __shared__ float t[32][33];
    const int n0 = blockIdx.x * 32, k0 = blockIdx.y * 32;
    const int tx = threadIdx.x & 31, ty = threadIdx.x >> 5;
    #pragma unroll
    for (int i = 0; i < 4; i++) {
        int kk = ty + i * 8;
        t[kk][tx] = W[(size_t)(k0 + kk) * Nd + n0 + tx];
    }
    __syncthreads();
    #pragma unroll
    for (int i = 0; i < 4; i++) {
        int nn = ty + i * 8;
        Th[(size_t)(n0 + nn) * Kd + k0 + tx] = __float2half_rn(t[tx][nn]);
    }
}

// ---------------------------------------------------------------------------
// RMSNorm -> fp16
// ---------------------------------------------------------------------------
__global__ void __launch_bounds__(256)
rmsnorm_half(const float* __restrict__ in, const float* __restrict__ g,
             __half* __restrict__ outh)
{
    __shared__ float red[8];
    const int row = blockIdx.x;
    const int tid = threadIdx.x;
    const float4* inr = (const float4*)(in + (size_t)row * DMODEL);
    float4 v0 = inr[tid];
    float4 v1 = inr[tid + 256];
    float ss = v0.x*v0.x + v0.y*v0.y + v0.z*v0.z + v0.w*v0.w
             + v1.x*v1.x + v1.y*v1.y + v1.z*v1.z + v1.w*v1.w;
    #pragma unroll
    for (int o = 16; o; o >>= 1) ss += __shfl_xor_sync(0xffffffffu, ss, o);
    if ((tid & 31) == 0) red[tid >> 5] = ss;
    __syncthreads();
    float tot = red[0]+red[1]+red[2]+red[3]+red[4]+red[5]+red[6]+red[7];
    float rs = rsqrtf(tot * (1.0f / DMODEL) + 1e-8f);

    const float4* gr = (const float4*)g;
    float4 ga = gr[tid], gb = gr[tid + 256];
    __half2* oh2 = (__half2*)(outh + (size_t)row * DMODEL);
    float y[8] = { v0.x*rs*ga.x, v0.y*rs*ga.y, v0.z*rs*ga.z, v0.w*rs*ga.w,
                   v1.x*rs*gb.x, v1.y*rs*gb.y, v1.z*rs*gb.z, v1.w*rs*gb.w };
    #pragma unroll
    for (int p = 0; p < 4; p++) {
        __half2 hh;
        hh.x = __float2half_rn(y[p*2]);
        hh.y = __float2half_rn(y[p*2+1]);
        int base = (p < 2) ? (tid*2 + p) : ((tid+256)*2 + (p-2));
        oh2[base] = hh;
    }
}

// ---------------------------------------------------------------------------
// RoPE + fp16 conversion into [bh][L][HD] Q(scaled)/K/V buffers
// one thread per (b,l,h,i<64)
// ---------------------------------------------------------------------------
__global__ void __launch_bounds__(256)
rope_split_kernel(const float* __restrict__ qkv,
                  __half* __restrict__ Qf, __half* __restrict__ Kf,
                  __half* __restrict__ Vf)
{
    const long idx = (long)blockIdx.x * 256 + threadIdx.x;
    const int  i   = (int)(idx & 63);
    const int  h   = (int)((idx >> 6) & 15);
    const long bl  = idx >> 10;
    const long l   = bl & 2047;
    const long b   = bl >> 11;

    float freq = expf(-(float)i * 0.14391156642875464f);
    float angle = (float)l * freq;
    float s, c;
    sincosf(angle, &s, &c);

    const float* qp = qkv + bl * (3 * DMODEL) + h * HD + i;
    const float* kp = qp + DMODEL;
    const float* vp = qp + 2 * DMODEL;
    float q1 = qp[0], q2 = qp[64];
    float k1 = kp[0], k2 = kp[64];

    const float scale = 0.088388347648318447f;  // 1/sqrt(128)
    size_t base = ((size_t)(b * NH + h) * LSEQ + l) * HD + i;
    Qf[base]      = __float2half_rn((q1 * c - q2 * s) * scale);
    Qf[base + 64] = __float2half_rn((q2 * c + q1 * s) * scale);
    Kf[base]      = __float2half_rn(k1 * c - k2 * s);
    Kf[base + 64] = __float2half_rn(k2 * c + k1 * s);
    Vf[base]      = __float2half_rn(vp[0]);
    Vf[base + 64] = __float2half_rn(vp[64]);
}

// ---------------------------------------------------------------------------
// Flash attention v2: fp16 mma, causal. CTA = 64 q-rows, 4 warps (128 thr).
// Warp w owns q rows [16w,16w+16). S = Q K^T via mma; softmax on fragments;
// P repacked in registers as A-frag; O += P V with V loaded via ldmatrix.trans.
// smem: Q,K,V tiles 64x128 fp16 at pitch 272B (conflict-free ldmatrix).
// ---------------------------------------------------------------------------
#define FA_PITCH 272
#define FA_TILE  (64 * FA_PITCH)     // 17408
#define FA_SMEM  (3 * FA_TILE)       // 52224

__global__ void __launch_bounds__(128)
attn_mma(const __half* __restrict__ Qf, const __half* __restrict__ Kf,
         const __half* __restrict__ Vf, __half* __restrict__ O)
{
    extern __shared__ __align__(16) char fsm[];
    const uint32_t sQ = smem_u32(fsm);
    const uint32_t sK = sQ + FA_TILE;
    const uint32_t sV = sK + FA_TILE;
    const int tid  = threadIdx.x;
    const int lane = tid & 31;
    const int w    = tid >> 5;
    const int bh   = blockIdx.y;
    const int qi   = gridDim.x - 1 - blockIdx.x;   // heavy tiles first
    const int q0   = qi * 64;

    const __half* qb = Qf + (size_t)bh * LSEQ * HD;
    const __half* kb = Kf + (size_t)bh * LSEQ * HD;
    const __half* vb = Vf + (size_t)bh * LSEQ * HD;

    // load Q tile
    #pragma unroll
    for (int i = 0; i < 8; i++) {
        int e = tid + i * 128;
        int r = e >> 4, cc = e & 15;
        cp16(sQ + r * FA_PITCH + cc * 16, qb + (size_t)(q0 + r) * HD + cc * 8);
    }
    asm volatile("cp.async.commit_group;" ::: "memory");

    const int qg0 = q0 + w * 16 + (lane >> 2);
    const int qg1 = qg0 + 8;

    const uint32_t a_off = (uint32_t)((w * 16 + (lane & 7) + ((lane >> 3) & 1) * 8) * FA_PITCH
                                      + (lane >> 4) * 16);
    const uint32_t b_off = (uint32_t)((lane & 7) * FA_PITCH + ((lane >> 3) & 1) * 16);
    const uint32_t v_off = (uint32_t)((lane & 15) * FA_PITCH);

    float oacc[16][4];
    #pragma unroll
    for (int i = 0; i < 16; i++)
        #pragma unroll
        for (int q = 0; q < 4; q++) oacc[i][q] = 0.f;
    float m0 = -1e30f, m1 = -1e30f, l0 = 0.f, l1 = 0.f;

    for (int kt = 0; kt <= qi; kt++) {
        const int k0 = kt * 64;
        #pragma unroll
        for (int i = 0; i < 8; i++) {
            int e = tid + i * 128;
            int r = e >> 4, cc = e & 15;
            size_t go = (size_t)(k0 + r) * HD + cc * 8;
            cp16(sK + r * FA_PITCH + cc * 16, kb + go);
            cp16(sV + r * FA_PITCH + cc * 16, vb + go);
        }
        asm volatile("cp.async.commit_group;" ::: "memory");
        asm volatile("cp.async.wait_group 0;" ::: "memory");
        __syncthreads();

        // S = Q K^T
        float sacc[8][4];
        #pragma unroll
        for (int nt = 0; nt < 8; nt++)
            #pragma unroll
            for (int q = 0; q < 4; q++) sacc[nt][q] = 0.f;

        #pragma unroll
        for (int ks = 0; ks < 8; ks++) {
            uint32_t aq[4];
            ldsm_x4(aq, sQ + a_off + ks * 32);
            #pragma unroll
            for (int nt = 0; nt < 8; nt++) {
                uint32_t bk[2];
                ldsm_x2(bk, sK + nt * (8 * FA_PITCH) + b_off + ks * 32);
                mma_f32(sacc[nt], aq, bk);
            }
        }

        // causal mask (only the diagonal tile)
        if (kt == qi) {
            #pragma unroll
            for (int nt = 0; nt < 8; nt++) {
                int jg = k0 + nt * 8 + (lane & 3) * 2;
                if (jg > qg0)     sacc[nt][0] = -1e30f;
                if (jg + 1 > qg0) sacc[nt][1] = -1e30f;
                if (jg > qg1)     sacc[nt][2] = -1e30f;
                if (jg + 1 > qg1) sacc[nt][3] = -1e30f;
            }
        }

        // online softmax
        float tm0 = -1e30f, tm1 = -1e30f;
        #pragma unroll
        for (int nt = 0; nt < 8; nt++) {
            tm0 = fmaxf(tm0, fmaxf(sacc[nt][0], sacc[nt][1]));
            tm1 = fmaxf(tm1, fmaxf(sacc[nt][2], sacc[nt][3]));
        }
        tm0 = fmaxf(tm0, __shfl_xor_sync(0xffffffffu, tm0, 1));
        tm0 = fmaxf(tm0, __shfl_xor_sync(0xffffffffu, tm0, 2));
        tm1 = fmaxf(tm1, __shfl_xor_sync(0xffffffffu, tm1, 1));
        tm1 = fmaxf(tm1, __shfl_xor_sync(0xffffffffu, tm1, 2));

        float mn0 = fmaxf(m0, tm0), mn1 = fmaxf(m1, tm1);
        float c0 = __expf(m0 - mn0), c1 = __expf(m1 - mn1);
        float ps0 = 0.f, ps1 = 0.f;
        #pragma unroll
        for (int nt = 0; nt < 8; nt++) {
            sacc[nt][0] = __expf(sacc[nt][0] - mn0);
            sacc[nt][1] = __expf(sacc[nt][1] - mn0);
            sacc[nt][2] = __expf(sacc[nt][2] - mn1);
            sacc[nt][3] = __expf(sacc[nt][3] - mn1);
            ps0 += sacc[nt][0] + sacc[nt][1];
            ps1 += sacc[nt][2] + sacc[nt][3];
        }
        ps0 += __shfl_xor_sync(0xffffffffu, ps0, 1);
        ps0 += __shfl_xor_sync(0xffffffffu, ps0, 2);
        ps1 += __shfl_xor_sync(0xffffffffu, ps1, 1);
        ps1 += __shfl_xor_sync(0xffffffffu, ps1, 2);
        l0 = l0 * c0 + ps0;  m0 = mn0;
        l1 = l1 * c1 + ps1;  m1 = mn1;
        #pragma unroll
        for (int nt2 = 0; nt2 < 16; nt2++) {
            oacc[nt2][0] *= c0;  oacc[nt2][1] *= c0;
            oacc[nt2][2] *= c1;  oacc[nt2][3] *= c1;
        }

        // repack P (S acc) as A-fragments for PV
        uint32_t pa[4][4];
        #pragma unroll
        for (int kp = 0; kp < 4; kp++) {
            pa[kp][0] = pack2h(sacc[2*kp][0],   sacc[2*kp][1]);
            pa[kp][1] = pack2h(sacc[2*kp][2],   sacc[2*kp][3]);
            pa[kp][2] = pack2h(sacc[2*kp+1][0], sacc[2*kp+1][1]);
            pa[kp][3] = pack2h(sacc[2*kp+1][2], sacc[2*kp+1][3]);
        }

        // O += P V  (V loaded transposed: B[n=hd][k=seq])
        #pragma unroll
        for (int kp = 0; kp < 4; kp++) {
            const uint32_t vb_ = sV + (uint32_t)(kp * 16) * FA_PITCH + v_off;
            #pragma unroll
            for (int nt2 = 0; nt2 < 16; nt2++) {
                uint32_t bv[2];
                ldsm_x2t(bv, vb_ + nt2 * 16);
                mma_f32(oacc[nt2], pa[kp], bv);
            }
        }
        __syncthreads();   // protect K,V before next tile's loads
    }

    // write O (fp16, row-major [4096][2048], col offset h*128)
    float i0 = 1.f / l0, i1 = 1.f / l1;
    const int b  = bh >> 4;
    const int hh = bh & 15;
    size_t row0 = (size_t)b * LSEQ + qg0;
    size_t row1 = row0 + 8;
    #pragma unroll
    for (int nt2 = 0; nt2 < 16; nt2++) {
        int col = hh * HD + nt2 * 8 + (lane & 3) * 2;
        __half2 h0, h1;
        h0.x = __float2half_rn(oacc[nt2][0] * i0);
        h0.y = __float2half_rn(oacc[nt2][1] * i0);
        h1.x = __float2half_rn(oacc[nt2][2] * i1);
        h1.y = __float2half_rn(oacc[nt2][3] * i1);
        *(__half2*)(O + row0 * DMODEL + col) = h0;
        *(__half2*)(O + row1 * DMODEL + col) = h1;
    }
}

// ---------------------------------------------------------------------------
// SwiGLU -> fp16
// ---------------------------------------------------------------------------
__global__ void __launch_bounds__(256)
swiglu_half(const float* __restrict__ P, __half* __restrict__ Fh)
{
    size_t i4 = (size_t)blockIdx.x * 256 + threadIdx.x;
    if (i4 >= (size_t)ROWS * 4 * DMODEL / 4) return;
    size_t rr  = i4 >> 11;
    size_t kk4 = i4 & 2047;
    const float4 gt = *(const float4*)(P + rr * 16384 + kk4 * 4);
    const float4 vl = *(const float4*)(P + rr * 16384 + 8192 + kk4 * 4);
    float f[4];
    f[0] = gt.x / (1.f + __expf(-gt.x)) * vl.x;
    f[1] = gt.y / (1.f + __expf(-gt.y)) * vl.y;
    f[2] = gt.z / (1.f + __expf(-gt.z)) * vl.z;
    f[3] = gt.w / (1.f + __expf(-gt.w)) * vl.w;
    size_t ob = rr * 8192 + kk4 * 4;
    __half2* fh2 = (__half2*)(Fh + ob);
    #pragma unroll
    for (int p = 0; p < 2; p++) {
        __half2 hh;
        hh.x = __float2half_rn(f[p*2]);
        hh.y = __float2half_rn(f[p*2+1]);
        fh2[p] = hh;
    }
}

// ---------------------------------------------------------------------------
// Host launcher
// ---------------------------------------------------------------------------
extern "C" void kernel_launch(void* const* d_in, const int* in_sizes, int n_in,
                              void* d_out, int out_size)
{
    const float* x    = (const float*)d_in[0];
    const float* Wqkv = (const float*)d_in[1];
    const float* bqkv = (const float*)d_in[2];
    const float* Wo   = (const float*)d_in[3];
    const float* bo   = (const float*)d_in[4];
    const float* g1   = (const float*)d_in[5];
    const float* g2   = (const float*)d_in[6];
    const float* Wp   = (const float*)d_in[7];
    const float* bp   = (const float*)d_in[8];
    const float* Wff  = (const float*)d_in[9];
    const float* bff  = (const float*)d_in[10];
    float* out = (float*)d_out;

    float *p_qkv, *p_x2, *p_p;
    __half *p_xn, *p_o, *p_ff, *p_qf, *p_kf, *p_vf;
    __half *p_wqkv, *p_wo, *p_wp, *p_wff;
    cudaGetSymbolAddress((void**)&p_qkv, g_qkv);
    cudaGetSymbolAddress((void**)&p_x2,  g_x2);
    cudaGetSymbolAddress((void**)&p_p,   g_p);
    cudaGetSymbolAddress((void**)&p_xn,  g_xn);
    cudaGetSymbolAddress((void**)&p_o,   g_o);
    cudaGetSymbolAddress((void**)&p_ff,  g_ff);
    cudaGetSymbolAddress((void**)&p_qf,  g_qf);
    cudaGetSymbolAddress((void**)&p_kf,  g_kf);
    cudaGetSymbolAddress((void**)&p_vf,  g_vf);
    cudaGetSymbolAddress((void**)&p_wqkv, g_wqkv);
    cudaGetSymbolAddress((void**)&p_wo,   g_wo);
    cudaGetSymbolAddress((void**)&p_wp,   g_wp);
    cudaGetSymbolAddress((void**)&p_wff,  g_wff);

    cudaFuncSetAttribute(attn_mma,    cudaFuncAttributeMaxDynamicSharedMemorySize, FA_SMEM);
    cudaFuncSetAttribute(gemm_kernel, cudaFuncAttributeMaxDynamicSharedMemorySize, GSMEM);

    // Weight transposition (fp16)
    transp_half<<<dim3(3 * DMODEL / 32, DMODEL / 32), 256>>>(Wqkv, p_wqkv, DMODEL, 3 * DMODEL);
    transp_half<<<dim3(DMODEL / 32, DMODEL / 32), 256>>>(Wo, p_wo, DMODEL, DMODEL);
    transp_half<<<dim3(8 * DMODEL / 32, DMODEL / 32), 256>>>(Wp, p_wp, DMODEL, 8 * DMODEL);
    transp_half<<<dim3(DMODEL / 32, 4 * DMODEL / 32), 256>>>(Wff, p_wff, 4 * DMODEL, DMODEL);

    // 1. pre-norm (-> fp16)
    rmsnorm_half<<<ROWS, 256>>>(x, g1, p_xn);

    // 2. QKV projection
    gemm_kernel<<<dim3(3 * DMODEL / 128, ROWS / 128), 512, GSMEM>>>(
        p_xn, p_wqkv, bqkv, nullptr, p_qkv, DMODEL, 3 * DMODEL);

    // 3. RoPE + split to fp16 Q(scaled)/K/V per-head buffers
    rope_split_kernel<<<(ROWS * NH * 64) / 256, 256>>>(p_qkv, p_qf, p_kf, p_vf);

    // 4. causal flash attention (fp16 mma) -> fp16 O
    attn_mma<<<dim3(LSEQ / 64, BD * NH), 128, FA_SMEM>>>(p_qf, p_kf, p_vf, p_o);

    // 5. output projection + residual
    gemm_kernel<<<dim3(DMODEL / 128, ROWS / 128), 512, GSMEM>>>(
        p_o, p_wo, bo, x, p_x2, DMODEL, DMODEL);

    // 6. second pre-norm (-> fp16)
    rmsnorm_half<<<ROWS, 256>>>(p_x2, g2, p_xn);

    // 7. FFN up-projection
    gemm_kernel<<<dim3(8 * DMODEL / 128, ROWS / 128), 512, GSMEM>>>(
        p_xn, p_wp, bp, nullptr, p_p, DMODEL, 8 * DMODEL);

    // 8. SwiGLU (-> fp16)
    swiglu_half<<<(ROWS * 4 * DMODEL / 4) / 256, 256>>>(p_p, p_ff);

    // 9. FFN down-projection + residual -> output
    gemm_kernel<<<dim3(DMODEL / 128, ROWS / 128), 512, GSMEM>>>(
        p_ff, p_wff, bff, p_x2, out, 4 * DMODEL, DMODEL);
}

// round 14
// speedup vs baseline: 3.3552x; 1.0689x over previous
#include <cuda_runtime.h>
#include <cuda_fp16.h>
#include <math.h>
#include <stdint.h>

// ---------------------------------------------------------------------------
// Problem constants
// ---------------------------------------------------------------------------
#define BD      2
#define LSEQ    2048
#define DMODEL  2048
#define NH      16
#define HD      128
#define ROWS    (BD * LSEQ)      // 4096

// ---------------------------------------------------------------------------
// Scratch (device globals -- no allocation allowed)
// ---------------------------------------------------------------------------
__device__ float g_qkv[ROWS * 3 * DMODEL];                 // fp32
__device__ float g_x2 [ROWS * DMODEL];

__device__ __half g_xn [ROWS * DMODEL];
__device__ __half g_o  [ROWS * DMODEL];
__device__ __half g_ff [(size_t)ROWS * 4 * DMODEL];
__device__ __half g_qf [ROWS * DMODEL];   // [bh][L][HD], q pre-scaled + roped
__device__ __half g_kf [ROWS * DMODEL];   // [bh][L][HD], roped
__device__ __half g_vf [ROWS * DMODEL];   // [bh][L][HD]
// transposed weights [N, K] fp16
__device__ __half g_wqkv[3 * DMODEL * DMODEL];
__device__ __half g_wo  [DMODEL * DMODEL];
__device__ __half g_wp  [(size_t)8 * DMODEL * DMODEL];
__device__ __half g_wff [(size_t)4 * DMODEL * DMODEL];

// ---------------------------------------------------------------------------
// Helpers
// ---------------------------------------------------------------------------
__device__ __forceinline__ uint32_t smem_u32(const void* p) {
    uint32_t a;
    asm("{ .reg .u64 t; cvta.to.shared.u64 t, %1; cvt.u32.u64 %0, t; }"
        : "=r"(a) : "l"(p));
    return a;
}
__device__ __forceinline__ void cp16(uint32_t dst, const void* src) {
    asm volatile("cp.async.cg.shared.global [%0], [%1], 16;" :: "r"(dst), "l"(src));
}
__device__ __forceinline__ void ldsm_x4(uint32_t* r, uint32_t a) {
    asm volatile("ldmatrix.sync.aligned.m8n8.x4.shared.b16 {%0,%1,%2,%3}, [%4];"
        : "=r"(r[0]), "=r"(r[1]), "=r"(r[2]), "=r"(r[3]) : "r"(a));
}
__device__ __forceinline__ void ldsm_x2(uint32_t* r, uint32_t a) {
    asm volatile("ldmatrix.sync.aligned.m8n8.x2.shared.b16 {%0,%1}, [%2];"
        : "=r"(r[0]), "=r"(r[1]) : "r"(a));
}
__device__ __forceinline__ void ldsm_x2t(uint32_t* r, uint32_t a) {
    asm volatile("ldmatrix.sync.aligned.m8n8.x2.trans.shared.b16 {%0,%1}, [%2];"
        : "=r"(r[0]), "=r"(r[1]) : "r"(a));
}
__device__ __forceinline__ void mma_f32(float* d, const uint32_t* a, const uint32_t* b) {
    asm volatile("mma.sync.aligned.m16n8k16.row.col.f32.f16.f16.f32 "
        "{%0,%1,%2,%3}, {%4,%5,%6,%7}, {%8,%9}, {%0,%1,%2,%3};"
        : "+f"(d[0]), "+f"(d[1]), "+f"(d[2]), "+f"(d[3])
        : "r"(a[0]), "r"(a[1]), "r"(a[2]), "r"(a[3]), "r"(b[0]), "r"(b[1]));
}
__device__ __forceinline__ uint32_t pack2h(float a, float b) {
    __half2 h = __floats2half2_rn(a, b);
    return *(uint32_t*)&h;
}
__device__ __forceinline__ float silu_f(float x) {
    return x / (1.f + __expf(-x));
}

// ---------------------------------------------------------------------------
// fp16 mma GEMM: C[M,N] = A[M,K] @ B[N,K]^T + bias (+res)
// CTA 128x128, 16 warps, warp tile 32x32, 512 threads, K-chunk 32,
// 4-stage cp.async (80KB smem). Pitch 80B: ldmatrix conflict-free.
// ---------------------------------------------------------------------------
#define GK       32
#define APITCH_B 80
#define COMP_B   10240
#define STAGE_B  20480
#define NSTAGE   4
#define GSMEM    (NSTAGE * STAGE_B)   // 81920

__device__ __forceinline__ void g_load_chunk(
    uint32_t st, int c, int tid,
    const __half* __restrict__ A, const __half* __restrict__ B,
    int K, int m0, int n0)
{
    const int k0 = c * GK;
    int r = tid >> 2, cc = tid & 3;
    uint32_t so = (uint32_t)(r * APITCH_B + cc * 16);
    cp16(st + so,          A + (size_t)(m0 + r) * K + k0 + cc * 8);
    cp16(st + COMP_B + so, B + (size_t)(n0 + r) * K + k0 + cc * 8);
    asm volatile("cp.async.commit_group;" ::: "memory");
}

__global__ void __launch_bounds__(512)
gemm_kernel(const __half* __restrict__ A, const __half* __restrict__ B,
            const float* __restrict__ bias, const float* __restrict__ res,
            float* __restrict__ C, int K, int N)
{
    extern __shared__ __align__(16) char sm_[];
    const uint32_t sb = smem_u32(sm_);
    const int tid  = threadIdx.x;
    const int lane = tid & 31;
    const int wid  = tid >> 5;
    const int wm   = wid >> 2;
    const int wn   = wid & 3;
    const int m0 = blockIdx.y << 7;
    const int n0 = blockIdx.x << 7;
    const int NC = K / GK;

    float acc[2][4][4];
    #pragma unroll
    for (int i = 0; i < 2; i++)
        #pragma unroll
        for (int j = 0; j < 4; j++)
            #pragma unroll
            for (int q = 0; q < 4; q++) acc[i][j][q] = 0.f;

    g_load_chunk(sb,               0, tid, A, B, K, m0, n0);
    g_load_chunk(sb + STAGE_B,     1, tid, A, B, K, m0, n0);
    g_load_chunk(sb + 2 * STAGE_B, 2, tid, A, B, K, m0, n0);

    const int rowA  = (lane & 7) + ((lane >> 3) & 1) * 8;
    const int kaddA = (lane >> 4) * 16;
    const uint32_t a_ld = (uint32_t)((wm * 32 + rowA) * APITCH_B + kaddA);
    const int rowB  = lane & 7;
    const int kaddB = ((lane >> 3) & 1) * 16;
    const uint32_t b_ld = (uint32_t)((wn * 32 + rowB) * APITCH_B + kaddB);

    for (int c = 0; c < NC; c++) {
        asm volatile("cp.async.wait_group 2;" ::: "memory");
        __syncthreads();

        if (c + 3 < NC)
            g_load_chunk(sb + (uint32_t)((c + 3) & 3) * STAGE_B, c + 3, tid,
                         A, B, K, m0, n0);

        const uint32_t st = sb + (uint32_t)(c & 3) * STAGE_B;

        #pragma unroll
        for (int kh = 0; kh < 2; kh++) {
            const uint32_t abase = st + a_ld + kh * 32;
            const uint32_t bbase = st + COMP_B + b_ld + kh * 32;

            uint32_t ar[2][4], br[4][2];
            #pragma unroll
            for (int mt = 0; mt < 2; mt++)
                ldsm_x4(ar[mt], abase + mt * (16 * APITCH_B));
            #pragma unroll
            for (int nt = 0; nt < 4; nt++)
                ldsm_x2(br[nt], bbase + nt * (8 * APITCH_B));

            #pragma unroll
            for (int mt = 0; mt < 2; mt++)
                #pragma unroll
                for (int nt = 0; nt < 4; nt++)
                    mma_f32(acc[mt][nt], ar[mt], br[nt]);
        }
    }

    #pragma unroll
    for (int mt = 0; mt < 2; mt++) {
        #pragma unroll
        for (int nt = 0; nt < 4; nt++) {
            const int rg = m0 + wm * 32 + mt * 16 + (lane >> 2);
            const int cg = n0 + wn * 32 + nt * 8 + (lane & 3) * 2;
            float2 bv = *(const float2*)(bias + cg);
            float2 o0, o1;
            o0.x = acc[mt][nt][0] + bv.x;  o0.y = acc[mt][nt][1] + bv.y;
            o1.x = acc[mt][nt][2] + bv.x;  o1.y = acc[mt][nt][3] + bv.y;
            if (res) {
                float2 r0 = *(const float2*)(res + (size_t)rg * N + cg);
                float2 r1 = *(const float2*)(res + (size_t)(rg + 8) * N + cg);
                o0.x += r0.x; o0.y += r0.y;
                o1.x += r1.x; o1.y += r1.y;
            }
            *(float2*)(C + (size_t)rg * N + cg)       = o0;
            *(float2*)(C + (size_t)(rg + 8) * N + cg) = o1;
        }
    }
}

// ---------------------------------------------------------------------------
// Fused FFN-up GEMM + SwiGLU: for col block j, computes gate (Wp rows j)
// and value (Wp rows j+8192) tiles over the same A stripe, then emits
// silu(gate)*value as fp16 into FF[M, 8192].
// smem/stage: A 10KB + Bg 10KB + Bv 10KB = 30KB; 4 stages = 120KB.
// ---------------------------------------------------------------------------
#define FSTAGE_B 30720
#define FGSMEM   (NSTAGE * FSTAGE_B)   // 122880

__device__ __forceinline__ void f_load_chunk(
    uint32_t st, int c, int tid,
    const __half* __restrict__ A, const __half* __restrict__ Bg,
    const __half* __restrict__ Bv, int K, int m0, int n0)
{
    const int k0 = c * GK;
    int r = tid >> 2, cc = tid & 3;
    uint32_t so = (uint32_t)(r * APITCH_B + cc * 16);
    size_t goA = (size_t)(m0 + r) * K + k0 + cc * 8;
    size_t goB = (size_t)(n0 + r) * K + k0 + cc * 8;
    cp16(st + so,              A  + goA);
    cp16(st + COMP_B + so,     Bg + goB);
    cp16(st + 2 * COMP_B + so, Bv + goB);
    asm volatile("cp.async.commit_group;" ::: "memory");
}

__global__ void __launch_bounds__(512)
gemm_ffn_kernel(const __half* __restrict__ A, const __half* __restrict__ Wp,
                const float* __restrict__ bp, __half* __restrict__ FF, int K)
{
    extern __shared__ __align__(16) char sm_[];
    const uint32_t sb = smem_u32(sm_);
    const int tid  = threadIdx.x;
    const int lane = tid & 31;
    const int wid  = tid >> 5;
    const int wm   = wid >> 2;
    const int wn   = wid & 3;
    const int m0 = blockIdx.y << 7;
    const int n0 = blockIdx.x << 7;          // gate col block; value at n0+8192
    const int NC = K / GK;

    const __half* Bg = Wp;                                  // rows [0,8192)
    const __half* Bv = Wp + (size_t)8192 * K;               // rows [8192,16384)

    float accg[2][4][4], accv[2][4][4];
    #pragma unroll
    for (int i = 0; i < 2; i++)
        #pragma unroll
        for (int j = 0; j < 4; j++)
            #pragma unroll
            for (int q = 0; q < 4; q++) { accg[i][j][q] = 0.f; accv[i][j][q] = 0.f; }

    f_load_chunk(sb,                0, tid, A, Bg, Bv, K, m0, n0);
    f_load_chunk(sb + FSTAGE_B,     1, tid, A, Bg, Bv, K, m0, n0);
    f_load_chunk(sb + 2 * FSTAGE_B, 2, tid, A, Bg, Bv, K, m0, n0);

    const int rowA  = (lane & 7) + ((lane >> 3) & 1) * 8;
    const int kaddA = (lane >> 4) * 16;
    const uint32_t a_ld = (uint32_t)((wm * 32 + rowA) * APITCH_B + kaddA);
    const int rowB  = lane & 7;
    const int kaddB = ((lane >> 3) & 1) * 16;
    const uint32_t b_ld = (uint32_t)((wn * 32 + rowB) * APITCH_B + kaddB);

    for (int c = 0; c < NC; c++) {
        asm volatile("cp.async.wait_group 2;" ::: "memory");
        __syncthreads();

        if (c + 3 < NC)
            f_load_chunk(sb + (uint32_t)((c + 3) & 3) * FSTAGE_B, c + 3, tid,
                         A, Bg, Bv, K, m0, n0);

        const uint32_t st = sb + (uint32_t)(c & 3) * FSTAGE_B;

        #pragma unroll
        for (int kh = 0; kh < 2; kh++) {
            const uint32_t abase = st + a_ld + kh * 32;
            const uint32_t gbase = st + COMP_B + b_ld + kh * 32;
            const uint32_t vbase = st + 2 * COMP_B + b_ld + kh * 32;

            uint32_t ar[2][4];
            #pragma unroll
            for (int mt = 0; mt < 2; mt++)
                ldsm_x4(ar[mt], abase + mt * (16 * APITCH_B));

            #pragma unroll
            for (int nt = 0; nt < 4; nt++) {
                uint32_t bg[2], bv_[2];
                ldsm_x2(bg,  gbase + nt * (8 * APITCH_B));
                ldsm_x2(bv_, vbase + nt * (8 * APITCH_B));
                #pragma unroll
                for (int mt = 0; mt < 2; mt++) {
                    mma_f32(accg[mt][nt], ar[mt], bg);
                    mma_f32(accv[mt][nt], ar[mt], bv_);
                }
            }
        }
    }

    // epilogue: FF = silu(gate + bg) * (value + bv)  -> fp16, row width 8192
    #pragma unroll
    for (int mt = 0; mt < 2; mt++) {
        #pragma unroll
        for (int nt = 0; nt < 4; nt++) {
            const int rg = m0 + wm * 32 + mt * 16 + (lane >> 2);
            const int cg = n0 + wn * 32 + nt * 8 + (lane & 3) * 2;
            float2 bg2 = *(const float2*)(bp + cg);
            float2 bv2 = *(const float2*)(bp + 8192 + cg);
            float f00 = silu_f(accg[mt][nt][0] + bg2.x) * (accv[mt][nt][0] + bv2.x);
            float f01 = silu_f(accg[mt][nt][1] + bg2.y) * (accv[mt][nt][1] + bv2.y);
            float f10 = silu_f(accg[mt][nt][2] + bg2.x) * (accv[mt][nt][2] + bv2.x);
            float f11 = silu_f(accg[mt][nt][3] + bg2.y) * (accv[mt][nt][3] + bv2.y);
            __half2 h0, h1;
            h0.x = __float2half_rn(f00);  h0.y = __float2half_rn(f01);
            h1.x = __float2half_rn(f10);  h1.y = __float2half_rn(f11);
            *(__half2*)(FF + (size_t)rg * 8192 + cg)       = h0;
            *(__half2*)(FF + (size_t)(rg + 8) * 8192 + cg) = h1;
        }
    }
}

// ---------------------------------------------------------------------------
// Weight transpose + fp16 round
// ---------------------------------------------------------------------------
__global__ void __launch_bounds__(256)
transp_half(const float* __restrict__ W, __half* __restrict__ Th, int Kd, int Nd)
{
    __shared__ float t[32][33];
    const int n0 = blockIdx.x * 32, k0 = blockIdx.y * 32;
    const int tx = threadIdx.x & 31, ty = threadIdx.x >> 5;
    #pragma unroll
    for (int i = 0; i < 4; i++) {
        int kk = ty + i * 8;
        t[kk][tx] = W[(size_t)(k0 + kk) * Nd + n0 + tx];
    }
    __syncthreads();
    #pragma unroll
    for (int i = 0; i < 4; i++) {
        int nn = ty + i * 8;
        Th[(size_t)(n0 + nn) * Kd + k0 + tx] = __float2half_rn(t[tx][nn]);
    }
}

// ---------------------------------------------------------------------------
// RMSNorm -> fp16
// ---------------------------------------------------------------------------
__global__ void __launch_bounds__(256)
rmsnorm_half(const float* __restrict__ in, const float* __restrict__ g,
             __half* __restrict__ outh)
{
    __shared__ float red[8];
    const int row = blockIdx.x;
    const int tid = threadIdx.x;
    const float4* inr = (const float4*)(in + (size_t)row * DMODEL);
    float4 v0 = inr[tid];
    float4 v1 = inr[tid + 256];
    float ss = v0.x*v0.x + v0.y*v0.y + v0.z*v0.z + v0.w*v0.w
             + v1.x*v1.x + v1.y*v1.y + v1.z*v1.z + v1.w*v1.w;
    #pragma unroll
    for (int o = 16; o; o >>= 1) ss += __shfl_xor_sync(0xffffffffu, ss, o);
    if ((tid & 31) == 0) red[tid >> 5] = ss;
    __syncthreads();
    float tot = red[0]+red[1]+red[2]+red[3]+red[4]+red[5]+red[6]+red[7];
    float rs = rsqrtf(tot * (1.0f / DMODEL) + 1e-8f);

    const float4* gr = (const float4*)g;
    float4 ga = gr[tid], gb = gr[tid + 256];
    __half2* oh2 = (__half2*)(outh + (size_t)row * DMODEL);
    float y[8] = { v0.x*rs*ga.x, v0.y*rs*ga.y, v0.z*rs*ga.z, v0.w*rs*ga.w,
                   v1.x*rs*gb.x, v1.y*rs*gb.y, v1.z*rs*gb.z, v1.w*rs*gb.w };
    #pragma unroll
    for (int p = 0; p < 4; p++) {
        __half2 hh;
        hh.x = __float2half_rn(y[p*2]);
        hh.y = __float2half_rn(y[p*2+1]);
        int base = (p < 2) ? (tid*2 + p) : ((tid+256)*2 + (p-2));
        oh2[base] = hh;
    }
}

// ---------------------------------------------------------------------------
// RoPE + fp16 conversion into [bh][L][HD] Q(scaled)/K/V buffers
// ---------------------------------------------------------------------------
__global__ void __launch_bounds__(256)
rope_split_kernel(const float* __restrict__ qkv,
                  __half* __restrict__ Qf, __half* __restrict__ Kf,
                  __half* __restrict__ Vf)
{
    const long idx = (long)blockIdx.x * 256 + threadIdx.x;
    const int  i   = (int)(idx & 63);
    const int  h   = (int)((idx >> 6) & 15);
    const long bl  = idx >> 10;
    const long l   = bl & 2047;
    const long b   = bl >> 11;

    float freq = expf(-(float)i * 0.14391156642875464f);
    float angle = (float)l * freq;
    float s, c;
    sincosf(angle, &s, &c);

    const float* qp = qkv + bl * (3 * DMODEL) + h * HD + i;
    const float* kp = qp + DMODEL;
    const float* vp = qp + 2 * DMODEL;
    float q1 = qp[0], q2 = qp[64];
    float k1 = kp[0], k2 = kp[64];

    const float scale = 0.088388347648318447f;  // 1/sqrt(128)
    size_t base = ((size_t)(b * NH + h) * LSEQ + l) * HD + i;
    Qf[base]      = __float2half_rn((q1 * c - q2 * s) * scale);
    Qf[base + 64] = __float2half_rn((q2 * c + q1 * s) * scale);
    Kf[base]      = __float2half_rn(k1 * c - k2 * s);
    Kf[base + 64] = __float2half_rn(k2 * c + k1 * s);
    Vf[base]      = __float2half_rn(vp[0]);
    Vf[base + 64] = __float2half_rn(vp[64]);
}

// ---------------------------------------------------------------------------
// Flash attention v2 (fp16 mma, causal) — from R13
// ---------------------------------------------------------------------------
#define FA_PITCH 272
#define FA_TILE  (64 * FA_PITCH)
#define FA_SMEM  (3 * FA_TILE)

__global__ void __launch_bounds__(128)
attn_mma(const __half* __restrict__ Qf, const __half* __restrict__ Kf,
         const __half* __restrict__ Vf, __half* __restrict__ O)
{
    extern __shared__ __align__(16) char fsm[];
    const uint32_t sQ = smem_u32(fsm);
    const uint32_t sK = sQ + FA_TILE;
    const uint32_t sV = sK + FA_TILE;
    const int tid  = threadIdx.x;
    const int lane = tid & 31;
    const int w    = tid >> 5;
    const int bh   = blockIdx.y;
    const int qi   = gridDim.x - 1 - blockIdx.x;
    const int q0   = qi * 64;

    const __half* qb = Qf + (size_t)bh * LSEQ * HD;
    const __half* kb = Kf + (size_t)bh * LSEQ * HD;
    const __half* vb = Vf + (size_t)bh * LSEQ * HD;

    #pragma unroll
    for (int i = 0; i < 8; i++) {
        int e = tid + i * 128;
        int r = e >> 4, cc = e & 15;
        cp16(sQ + r * FA_PITCH + cc * 16, qb + (size_t)(q0 + r) * HD + cc * 8);
    }
    asm volatile("cp.async.commit_group;" ::: "memory");

    const int qg0 = q0 + w * 16 + (lane >> 2);
    const int qg1 = qg0 + 8;

    const uint32_t a_off = (uint32_t)((w * 16 + (lane & 7) + ((lane >> 3) & 1) * 8) * FA_PITCH
                                      + (lane >> 4) * 16);
    const uint32_t b_off = (uint32_t)((lane & 7) * FA_PITCH + ((lane >> 3) & 1) * 16);
    const uint32_t v_off = (uint32_t)((lane & 15) * FA_PITCH);

    float oacc[16][4];
    #pragma unroll
    for (int i = 0; i < 16; i++)
        #pragma unroll
        for (int q = 0; q < 4; q++) oacc[i][q] = 0.f;
    float m0 = -1e30f, m1 = -1e30f, l0 = 0.f, l1 = 0.f;

    for (int kt = 0; kt <= qi; kt++) {
        const int k0 = kt * 64;
        #pragma unroll
        for (int i = 0; i < 8; i++) {
            int e = tid + i * 128;
            int r = e >> 4, cc = e & 15;
            size_t go = (size_t)(k0 + r) * HD + cc * 8;
            cp16(sK + r * FA_PITCH + cc * 16, kb + go);
            cp16(sV + r * FA_PITCH + cc * 16, vb + go);
        }
        asm volatile("cp.async.commit_group;" ::: "memory");
        asm volatile("cp.async.wait_group 0;" ::: "memory");
        __syncthreads();

        float sacc[8][4];
        #pragma unroll
        for (int nt = 0; nt < 8; nt++)
            #pragma unroll
            for (int q = 0; q < 4; q++) sacc[nt][q] = 0.f;

        #pragma unroll
        for (int ks = 0; ks < 8; ks++) {
            uint32_t aq[4];
            ldsm_x4(aq, sQ + a_off + ks * 32);
            #pragma unroll
            for (int nt = 0; nt < 8; nt++) {
                uint32_t bk[2];
                ldsm_x2(bk, sK + nt * (8 * FA_PITCH) + b_off + ks * 32);
                mma_f32(sacc[nt], aq, bk);
            }
        }

        if (kt == qi) {
            #pragma unroll
            for (int nt = 0; nt < 8; nt++) {
                int jg = k0 + nt * 8 + (lane & 3) * 2;
                if (jg > qg0)     sacc[nt][0] = -1e30f;
                if (jg + 1 > qg0) sacc[nt][1] = -1e30f;
                if (jg > qg1)     sacc[nt][2] = -1e30f;
                if (jg + 1 > qg1) sacc[nt][3] = -1e30f;
            }
        }

        float tm0 = -1e30f, tm1 = -1e30f;
        #pragma unroll
        for (int nt = 0; nt < 8; nt++) {
            tm0 = fmaxf(tm0, fmaxf(sacc[nt][0], sacc[nt][1]));
            tm1 = fmaxf(tm1, fmaxf(sacc[nt][2], sacc[nt][3]));
        }
        tm0 = fmaxf(tm0, __shfl_xor_sync(0xffffffffu, tm0, 1));
        tm0 = fmaxf(tm0, __shfl_xor_sync(0xffffffffu, tm0, 2));
        tm1 = fmaxf(tm1, __shfl_xor_sync(0xffffffffu, tm1, 1));
        tm1 = fmaxf(tm1, __shfl_xor_sync(0xffffffffu, tm1, 2));

        float mn0 = fmaxf(m0, tm0), mn1 = fmaxf(m1, tm1);
        float c0 = __expf(m0 - mn0), c1 = __expf(m1 - mn1);
        float ps0 = 0.f, ps1 = 0.f;
        #pragma unroll
        for (int nt = 0; nt < 8; nt++) {
            sacc[nt][0] = __expf(sacc[nt][0] - mn0);
            sacc[nt][1] = __expf(sacc[nt][1] - mn0);
            sacc[nt][2] = __expf(sacc[nt][2] - mn1);
            sacc[nt][3] = __expf(sacc[nt][3] - mn1);
            ps0 += sacc[nt][0] + sacc[nt][1];
            ps1 += sacc[nt][2] + sacc[nt][3];
        }
        ps0 += __shfl_xor_sync(0xffffffffu, ps0, 1);
        ps0 += __shfl_xor_sync(0xffffffffu, ps0, 2);
        ps1 += __shfl_xor_sync(0xffffffffu, ps1, 1);
        ps1 += __shfl_xor_sync(0xffffffffu, ps1, 2);
        l0 = l0 * c0 + ps0;  m0 = mn0;
        l1 = l1 * c1 + ps1;  m1 = mn1;
        #pragma unroll
        for (int nt2 = 0; nt2 < 16; nt2++) {
            oacc[nt2][0] *= c0;  oacc[nt2][1] *= c0;
            oacc[nt2][2] *= c1;  oacc[nt2][3] *= c1;
        }

        uint32_t pa[4][4];
        #pragma unroll
        for (int kp = 0; kp < 4; kp++) {
            pa[kp][0] = pack2h(sacc[2*kp][0],   sacc[2*kp][1]);
            pa[kp][1] = pack2h(sacc[2*kp][2],   sacc[2*kp][3]);
            pa[kp][2] = pack2h(sacc[2*kp+1][0], sacc[2*kp+1][1]);
            pa[kp][3] = pack2h(sacc[2*kp+1][2], sacc[2*kp+1][3]);
        }

        #pragma unroll
        for (int kp = 0; kp < 4; kp++) {
            const uint32_t vb_ = sV + (uint32_t)(kp * 16) * FA_PITCH + v_off;
            #pragma unroll
            for (int nt2 = 0; nt2 < 16; nt2++) {
                uint32_t bv[2];
                ldsm_x2t(bv, vb_ + nt2 * 16);
                mma_f32(oacc[nt2], pa[kp], bv);
            }
        }
        __syncthreads();
    }

    float i0 = 1.f / l0, i1 = 1.f / l1;
    const int b  = bh >> 4;
    const int hh = bh & 15;
    size_t row0 = (size_t)b * LSEQ + qg0;
    size_t row1 = row0 + 8;
    #pragma unroll
    for (int nt2 = 0; nt2 < 16; nt2++) {
        int col = hh * HD + nt2 * 8 + (lane & 3) * 2;
        __half2 h0, h1;
        h0.x = __float2half_rn(oacc[nt2][0] * i0);
        h0.y = __float2half_rn(oacc[nt2][1] * i0);
        h1.x = __float2half_rn(oacc[nt2][2] * i1);
        h1.y = __float2half_rn(oacc[nt2][3] * i1);
        *(__half2*)(O + row0 * DMODEL + col) = h0;
        *(__half2*)(O + row1 * DMODEL + col) = h1;
    }
}

// ---------------------------------------------------------------------------
// Host launcher
// ---------------------------------------------------------------------------
extern "C" void kernel_launch(void* const* d_in, const int* in_sizes, int n_in,
                              void* d_out, int out_size)
{
    const float* x    = (const float*)d_in[0];
    const float* Wqkv = (const float*)d_in[1];
    const float* bqkv = (const float*)d_in[2];
    const float* Wo   = (const float*)d_in[3];
    const float* bo   = (const float*)d_in[4];
    const float* g1   = (const float*)d_in[5];
    const float* g2   = (const float*)d_in[6];
    const float* Wp   = (const float*)d_in[7];
    const float* bp   = (const float*)d_in[8];
    const float* Wff  = (const float*)d_in[9];
    const float* bff  = (const float*)d_in[10];
    float* out = (float*)d_out;

    float *p_qkv, *p_x2;
    __half *p_xn, *p_o, *p_ff, *p_qf, *p_kf, *p_vf;
    __half *p_wqkv, *p_wo, *p_wp, *p_wff;
    cudaGetSymbolAddress((void**)&p_qkv, g_qkv);
    cudaGetSymbolAddress((void**)&p_x2,  g_x2);
    cudaGetSymbolAddress((void**)&p_xn,  g_xn);
    cudaGetSymbolAddress((void**)&p_o,   g_o);
    cudaGetSymbolAddress((void**)&p_ff,  g_ff);
    cudaGetSymbolAddress((void**)&p_qf,  g_qf);
    cudaGetSymbolAddress((void**)&p_kf,  g_kf);
    cudaGetSymbolAddress((void**)&p_vf,  g_vf);
    cudaGetSymbolAddress((void**)&p_wqkv, g_wqkv);
    cudaGetSymbolAddress((void**)&p_wo,   g_wo);
    cudaGetSymbolAddress((void**)&p_wp,   g_wp);
    cudaGetSymbolAddress((void**)&p_wff,  g_wff);

    cudaFuncSetAttribute(attn_mma,        cudaFuncAttributeMaxDynamicSharedMemorySize, FA_SMEM);
    cudaFuncSetAttribute(gemm_kernel,     cudaFuncAttributeMaxDynamicSharedMemorySize, GSMEM);
    cudaFuncSetAttribute(gemm_ffn_kernel, cudaFuncAttributeMaxDynamicSharedMemorySize, FGSMEM);

    // Weight transposition (fp16)
    transp_half<<<dim3(3 * DMODEL / 32, DMODEL / 32), 256>>>(Wqkv, p_wqkv, DMODEL, 3 * DMODEL);
    transp_half<<<dim3(DMODEL / 32, DMODEL / 32), 256>>>(Wo, p_wo, DMODEL, DMODEL);
    transp_half<<<dim3(8 * DMODEL / 32, DMODEL / 32), 256>>>(Wp, p_wp, DMODEL, 8 * DMODEL);
    transp_half<<<dim3(DMODEL / 32, 4 * DMODEL / 32), 256>>>(Wff, p_wff, 4 * DMODEL, DMODEL);

    // 1. pre-norm (-> fp16)
    rmsnorm_half<<<ROWS, 256>>>(x, g1, p_xn);

    // 2. QKV projection
    gemm_kernel<<<dim3(3 * DMODEL / 128, ROWS / 128), 512, GSMEM>>>(
        p_xn, p_wqkv, bqkv, nullptr, p_qkv, DMODEL, 3 * DMODEL);

    // 3. RoPE + split to fp16 Q(scaled)/K/V per-head buffers
    rope_split_kernel<<<(ROWS * NH * 64) / 256, 256>>>(p_qkv, p_qf, p_kf, p_vf);

    // 4. causal flash attention (fp16 mma) -> fp16 O
    attn_mma<<<dim3(LSEQ / 64, BD * NH), 128, FA_SMEM>>>(p_qf, p_kf, p_vf, p_o);

    // 5. output projection + residual
    gemm_kernel<<<dim3(DMODEL / 128, ROWS / 128), 512, GSMEM>>>(
        p_o, p_wo, bo, x, p_x2, DMODEL, DMODEL);

    // 6. second pre-norm (-> fp16)
    rmsnorm_half<<<ROWS, 256>>>(p_x2, g2, p_xn);

    // 7+8. FFN up-projection fused with SwiGLU (-> fp16 ff)
    gemm_ffn_kernel<<<dim3(4 * DMODEL / 128, ROWS / 128), 512, FGSMEM>>>(
        p_xn, p_wp, bp, p_ff, DMODEL);

    // 9. FFN down-projection + residual -> output
    gemm_kernel<<<dim3(DMODEL / 128, ROWS / 128), 512, GSMEM>>>(
        p_ff, p_wff, bff, p_x2, out, 4 * DMODEL, DMODEL);
}

// round 15
// speedup vs baseline: 3.4232x; 1.0203x over previous
#include <cuda_runtime.h>
#include <cuda_fp16.h>
#include <math.h>
#include <stdint.h>

// ---------------------------------------------------------------------------
// Problem constants
// ---------------------------------------------------------------------------
#define BD      2
#define LSEQ    2048
#define DMODEL  2048
#define NH      16
#define HD      128
#define ROWS    (BD * LSEQ)      // 4096

// ---------------------------------------------------------------------------
// Scratch (device globals -- no allocation allowed)
// ---------------------------------------------------------------------------
__device__ float  g_x2 [ROWS * DMODEL];

__device__ __half g_qkvh[ROWS * 3 * DMODEL];   // fp16 QKV (48 MB)
__device__ __half g_xn [ROWS * DMODEL];
__device__ __half g_o  [ROWS * DMODEL];
__device__ __half g_ff [(size_t)ROWS * 4 * DMODEL];
__device__ __half g_qf [ROWS * DMODEL];   // [bh][L][HD], q pre-scaled + roped
__device__ __half g_kf [ROWS * DMODEL];   // [bh][L][HD], roped
__device__ __half g_vf [ROWS * DMODEL];   // [bh][L][HD]
// transposed weights [N, K] fp16
__device__ __half g_wqkv[3 * DMODEL * DMODEL];
__device__ __half g_wo  [DMODEL * DMODEL];
__device__ __half g_wp  [(size_t)8 * DMODEL * DMODEL];
__device__ __half g_wff [(size_t)4 * DMODEL * DMODEL];

// ---------------------------------------------------------------------------
// Helpers
// ---------------------------------------------------------------------------
__device__ __forceinline__ uint32_t smem_u32(const void* p) {
    uint32_t a;
    asm("{ .reg .u64 t; cvta.to.shared.u64 t, %1; cvt.u32.u64 %0, t; }"
        : "=r"(a) : "l"(p));
    return a;
}
__device__ __forceinline__ void cp16(uint32_t dst, const void* src) {
    asm volatile("cp.async.cg.shared.global [%0], [%1], 16;" :: "r"(dst), "l"(src));
}
__device__ __forceinline__ void ldsm_x4(uint32_t* r, uint32_t a) {
    asm volatile("ldmatrix.sync.aligned.m8n8.x4.shared.b16 {%0,%1,%2,%3}, [%4];"
        : "=r"(r[0]), "=r"(r[1]), "=r"(r[2]), "=r"(r[3]) : "r"(a));
}
__device__ __forceinline__ void ldsm_x2(uint32_t* r, uint32_t a) {
    asm volatile("ldmatrix.sync.aligned.m8n8.x2.shared.b16 {%0,%1}, [%2];"
        : "=r"(r[0]), "=r"(r[1]) : "r"(a));
}
__device__ __forceinline__ void ldsm_x2t(uint32_t* r, uint32_t a) {
    asm volatile("ldmatrix.sync.aligned.m8n8.x2.trans.shared.b16 {%0,%1}, [%2];"
        : "=r"(r[0]), "=r"(r[1]) : "r"(a));
}
__device__ __forceinline__ void mma_f32(float* d, const uint32_t* a, const uint32_t* b) {
    asm volatile("mma.sync.aligned.m16n8k16.row.col.f32.f16.f16.f32 "
        "{%0,%1,%2,%3}, {%4,%5,%6,%7}, {%8,%9}, {%0,%1,%2,%3};"
        : "+f"(d[0]), "+f"(d[1]), "+f"(d[2]), "+f"(d[3])
        : "r"(a[0]), "r"(a[1]), "r"(a[2]), "r"(a[3]), "r"(b[0]), "r"(b[1]));
}
__device__ __forceinline__ uint32_t pack2h(float a, float b) {
    __half2 h = __floats2half2_rn(a, b);
    return *(uint32_t*)&h;
}
__device__ __forceinline__ float silu_f(float x) {
    return x / (1.f + __expf(-x));
}

// ---------------------------------------------------------------------------
// fp16 mma GEMM: C[M,N] = A[M,K] @ B[N,K]^T + bias (+res)
// OUTH=0: fp32 C (+ optional fp32 res). OUTH=1: fp16 C, no res.
// CTA 128x128, 16 warps, warp tile 32x32, 512 threads, K-chunk 32,
// 4-stage cp.async (80KB smem). Pitch 80B: ldmatrix conflict-free.
// ---------------------------------------------------------------------------
#define GK       32
#define APITCH_B 80
#define COMP_B   10240
#define STAGE_B  20480
#define NSTAGE   4
#define GSMEM    (NSTAGE * STAGE_B)   // 81920

__device__ __forceinline__ void g_load_chunk(
    uint32_t st, int c, int tid,
    const __half* __restrict__ A, const __half* __restrict__ B,
    int K, int m0, int n0)
{
    const int k0 = c * GK;
    int r = tid >> 2, cc = tid & 3;
    uint32_t so = (uint32_t)(r * APITCH_B + cc * 16);
    cp16(st + so,          A + (size_t)(m0 + r) * K + k0 + cc * 8);
    cp16(st + COMP_B + so, B + (size_t)(n0 + r) * K + k0 + cc * 8);
    asm volatile("cp.async.commit_group;" ::: "memory");
}

template<int OUTH>
__global__ void __launch_bounds__(512)
gemm_kernel(const __half* __restrict__ A, const __half* __restrict__ B,
            const float* __restrict__ bias, const float* __restrict__ res,
            void* __restrict__ Cv, int K, int N)
{
    extern __shared__ __align__(16) char sm_[];
    const uint32_t sb = smem_u32(sm_);
    const int tid  = threadIdx.x;
    const int lane = tid & 31;
    const int wid  = tid >> 5;
    const int wm   = wid >> 2;
    const int wn   = wid & 3;
    const int m0 = blockIdx.y << 7;
    const int n0 = blockIdx.x << 7;
    const int NC = K / GK;

    float acc[2][4][4];
    #pragma unroll
    for (int i = 0; i < 2; i++)
        #pragma unroll
        for (int j = 0; j < 4; j++)
            #pragma unroll
            for (int q = 0; q < 4; q++) acc[i][j][q] = 0.f;

    g_load_chunk(sb,               0, tid, A, B, K, m0, n0);
    g_load_chunk(sb + STAGE_B,     1, tid, A, B, K, m0, n0);
    g_load_chunk(sb + 2 * STAGE_B, 2, tid, A, B, K, m0, n0);

    const int rowA  = (lane & 7) + ((lane >> 3) & 1) * 8;
    const int kaddA = (lane >> 4) * 16;
    const uint32_t a_ld = (uint32_t)((wm * 32 + rowA) * APITCH_B + kaddA);
    const int rowB  = lane & 7;
    const int kaddB = ((lane >> 3) & 1) * 16;
    const uint32_t b_ld = (uint32_t)((wn * 32 + rowB) * APITCH_B + kaddB);

    for (int c = 0; c < NC; c++) {
        asm volatile("cp.async.wait_group 2;" ::: "memory");
        __syncthreads();

        if (c + 3 < NC)
            g_load_chunk(sb + (uint32_t)((c + 3) & 3) * STAGE_B, c + 3, tid,
                         A, B, K, m0, n0);

        const uint32_t st = sb + (uint32_t)(c & 3) * STAGE_B;

        #pragma unroll
        for (int kh = 0; kh < 2; kh++) {
            const uint32_t abase = st + a_ld + kh * 32;
            const uint32_t bbase = st + COMP_B + b_ld + kh * 32;

            uint32_t ar[2][4], br[4][2];
            #pragma unroll
            for (int mt = 0; mt < 2; mt++)
                ldsm_x4(ar[mt], abase + mt * (16 * APITCH_B));
            #pragma unroll
            for (int nt = 0; nt < 4; nt++)
                ldsm_x2(br[nt], bbase + nt * (8 * APITCH_B));

            #pragma unroll
            for (int mt = 0; mt < 2; mt++)
                #pragma unroll
                for (int nt = 0; nt < 4; nt++)
                    mma_f32(acc[mt][nt], ar[mt], br[nt]);
        }
    }

    #pragma unroll
    for (int mt = 0; mt < 2; mt++) {
        #pragma unroll
        for (int nt = 0; nt < 4; nt++) {
            const int rg = m0 + wm * 32 + mt * 16 + (lane >> 2);
            const int cg = n0 + wn * 32 + nt * 8 + (lane & 3) * 2;
            float2 bv = *(const float2*)(bias + cg);
            float2 o0, o1;
            o0.x = acc[mt][nt][0] + bv.x;  o0.y = acc[mt][nt][1] + bv.y;
            o1.x = acc[mt][nt][2] + bv.x;  o1.y = acc[mt][nt][3] + bv.y;
            if (OUTH) {
                __half* C = (__half*)Cv;
                __half2 h0, h1;
                h0.x = __float2half_rn(o0.x);  h0.y = __float2half_rn(o0.y);
                h1.x = __float2half_rn(o1.x);  h1.y = __float2half_rn(o1.y);
                *(__half2*)(C + (size_t)rg * N + cg)       = h0;
                *(__half2*)(C + (size_t)(rg + 8) * N + cg) = h1;
            } else {
                float* C = (float*)Cv;
                if (res) {
                    float2 r0 = *(const float2*)(res + (size_t)rg * N + cg);
                    float2 r1 = *(const float2*)(res + (size_t)(rg + 8) * N + cg);
                    o0.x += r0.x; o0.y += r0.y;
                    o1.x += r1.x; o1.y += r1.y;
                }
                *(float2*)(C + (size_t)rg * N + cg)       = o0;
                *(float2*)(C + (size_t)(rg + 8) * N + cg) = o1;
            }
        }
    }
}

// ---------------------------------------------------------------------------
// Fused FFN-up GEMM + SwiGLU (from R14)
// ---------------------------------------------------------------------------
#define FSTAGE_B 30720
#define FGSMEM   (NSTAGE * FSTAGE_B)   // 122880

__device__ __forceinline__ void f_load_chunk(
    uint32_t st, int c, int tid,
    const __half* __restrict__ A, const __half* __restrict__ Bg,
    const __half* __restrict__ Bv, int K, int m0, int n0)
{
    const int k0 = c * GK;
    int r = tid >> 2, cc = tid & 3;
    uint32_t so = (uint32_t)(r * APITCH_B + cc * 16);
    size_t goA = (size_t)(m0 + r) * K + k0 + cc * 8;
    size_t goB = (size_t)(n0 + r) * K + k0 + cc * 8;
    cp16(st + so,              A  + goA);
    cp16(st + COMP_B + so,     Bg + goB);
    cp16(st + 2 * COMP_B + so, Bv + goB);
    asm volatile("cp.async.commit_group;" ::: "memory");
}

__global__ void __launch_bounds__(512)
gemm_ffn_kernel(const __half* __restrict__ A, const __half* __restrict__ Wp,
                const float* __restrict__ bp, __half* __restrict__ FF, int K)
{
    extern __shared__ __align__(16) char sm_[];
    const uint32_t sb = smem_u32(sm_);
    const int tid  = threadIdx.x;
    const int lane = tid & 31;
    const int wid  = tid >> 5;
    const int wm   = wid >> 2;
    const int wn   = wid & 3;
    const int m0 = blockIdx.y << 7;
    const int n0 = blockIdx.x << 7;
    const int NC = K / GK;

    const __half* Bg = Wp;
    const __half* Bv = Wp + (size_t)8192 * K;

    float accg[2][4][4], accv[2][4][4];
    #pragma unroll
    for (int i = 0; i < 2; i++)
        #pragma unroll
        for (int j = 0; j < 4; j++)
            #pragma unroll
            for (int q = 0; q < 4; q++) { accg[i][j][q] = 0.f; accv[i][j][q] = 0.f; }

    f_load_chunk(sb,                0, tid, A, Bg, Bv, K, m0, n0);
    f_load_chunk(sb + FSTAGE_B,     1, tid, A, Bg, Bv, K, m0, n0);
    f_load_chunk(sb + 2 * FSTAGE_B, 2, tid, A, Bg, Bv, K, m0, n0);

    const int rowA  = (lane & 7) + ((lane >> 3) & 1) * 8;
    const int kaddA = (lane >> 4) * 16;
    const uint32_t a_ld = (uint32_t)((wm * 32 + rowA) * APITCH_B + kaddA);
    const int rowB  = lane & 7;
    const int kaddB = ((lane >> 3) & 1) * 16;
    const uint32_t b_ld = (uint32_t)((wn * 32 + rowB) * APITCH_B + kaddB);

    for (int c = 0; c < NC; c++) {
        asm volatile("cp.async.wait_group 2;" ::: "memory");
        __syncthreads();

        if (c + 3 < NC)
            f_load_chunk(sb + (uint32_t)((c + 3) & 3) * FSTAGE_B, c + 3, tid,
                         A, Bg, Bv, K, m0, n0);

        const uint32_t st = sb + (uint32_t)(c & 3) * FSTAGE_B;

        #pragma unroll
        for (int kh = 0; kh < 2; kh++) {
            const uint32_t abase = st + a_ld + kh * 32;
            const uint32_t gbase = st + COMP_B + b_ld + kh * 32;
            const uint32_t vbase = st + 2 * COMP_B + b_ld + kh * 32;

            uint32_t ar[2][4];
            #pragma unroll
            for (int mt = 0; mt < 2; mt++)
                ldsm_x4(ar[mt], abase + mt * (16 * APITCH_B));

            #pragma unroll
            for (int nt = 0; nt < 4; nt++) {
                uint32_t bg[2], bv_[2];
                ldsm_x2(bg,  gbase + nt * (8 * APITCH_B));
                ldsm_x2(bv_, vbase + nt * (8 * APITCH_B));
                #pragma unroll
                for (int mt = 0; mt < 2; mt++) {
                    mma_f32(accg[mt][nt], ar[mt], bg);
                    mma_f32(accv[mt][nt], ar[mt], bv_);
                }
            }
        }
    }

    #pragma unroll
    for (int mt = 0; mt < 2; mt++) {
        #pragma unroll
        for (int nt = 0; nt < 4; nt++) {
            const int rg = m0 + wm * 32 + mt * 16 + (lane >> 2);
            const int cg = n0 + wn * 32 + nt * 8 + (lane & 3) * 2;
            float2 bg2 = *(const float2*)(bp + cg);
            float2 bv2 = *(const float2*)(bp + 8192 + cg);
            float f00 = silu_f(accg[mt][nt][0] + bg2.x) * (accv[mt][nt][0] + bv2.x);
            float f01 = silu_f(accg[mt][nt][1] + bg2.y) * (accv[mt][nt][1] + bv2.y);
            float f10 = silu_f(accg[mt][nt][2] + bg2.x) * (accv[mt][nt][2] + bv2.x);
            float f11 = silu_f(accg[mt][nt][3] + bg2.y) * (accv[mt][nt][3] + bv2.y);
            __half2 h0, h1;
            h0.x = __float2half_rn(f00);  h0.y = __float2half_rn(f01);
            h1.x = __float2half_rn(f10);  h1.y = __float2half_rn(f11);
            *(__half2*)(FF + (size_t)rg * 8192 + cg)       = h0;
            *(__half2*)(FF + (size_t)(rg + 8) * 8192 + cg) = h1;
        }
    }
}

// ---------------------------------------------------------------------------
// Weight transpose + fp16 round
// ---------------------------------------------------------------------------
__global__ void __launch_bounds__(256)
transp_half(const float* __restrict__ W, __half* __restrict__ Th, int Kd, int Nd)
{
    __shared__ float t[32][33];
    const int n0 = blockIdx.x * 32, k0 = blockIdx.y * 32;
    const int tx = threadIdx.x & 31, ty = threadIdx.x >> 5;
    #pragma unroll
    for (int i = 0; i < 4; i++) {
        int kk = ty + i * 8;
        t[kk][tx] = W[(size_t)(k0 + kk) * Nd + n0 + tx];
    }
    __syncthreads();
    #pragma unroll
    for (int i = 0; i < 4; i++) {
        int nn = ty + i * 8;
        Th[(size_t)(n0 + nn) * Kd + k0 + tx] = __float2half_rn(t[tx][nn]);
    }
}

// ---------------------------------------------------------------------------
// RMSNorm -> fp16
// ---------------------------------------------------------------------------
__global__ void __launch_bounds__(256)
rmsnorm_half(const float* __restrict__ in, const float* __restrict__ g,
             __half* __restrict__ outh)
{
    __shared__ float red[8];
    const int row = blockIdx.x;
    const int tid = threadIdx.x;
    const float4* inr = (const float4*)(in + (size_t)row * DMODEL);
    float4 v0 = inr[tid];
    float4 v1 = inr[tid + 256];
    float ss = v0.x*v0.x + v0.y*v0.y + v0.z*v0.z + v0.w*v0.w
             + v1.x*v1.x + v1.y*v1.y + v1.z*v1.z + v1.w*v1.w;
    #pragma unroll
    for (int o = 16; o; o >>= 1) ss += __shfl_xor_sync(0xffffffffu, ss, o);
    if ((tid & 31) == 0) red[tid >> 5] = ss;
    __syncthreads();
    float tot = red[0]+red[1]+red[2]+red[3]+red[4]+red[5]+red[6]+red[7];
    float rs = rsqrtf(tot * (1.0f / DMODEL) + 1e-8f);

    const float4* gr = (const float4*)g;
    float4 ga = gr[tid], gb = gr[tid + 256];
    __half2* oh2 = (__half2*)(outh + (size_t)row * DMODEL);
    float y[8] = { v0.x*rs*ga.x, v0.y*rs*ga.y, v0.z*rs*ga.z, v0.w*rs*ga.w,
                   v1.x*rs*gb.x, v1.y*rs*gb.y, v1.z*rs*gb.z, v1.w*rs*gb.w };
    #pragma unroll
    for (int p = 0; p < 4; p++) {
        __half2 hh;
        hh.x = __float2half_rn(y[p*2]);
        hh.y = __float2half_rn(y[p*2+1]);
        int base = (p < 2) ? (tid*2 + p) : ((tid+256)*2 + (p-2));
        oh2[base] = hh;
    }
}

// ---------------------------------------------------------------------------
// RoPE (fp16 in) + split into [bh][L][HD] Q(scaled)/K/V buffers
// ---------------------------------------------------------------------------
__global__ void __launch_bounds__(256)
rope_split_kernel(const __half* __restrict__ qkv,
                  __half* __restrict__ Qf, __half* __restrict__ Kf,
                  __half* __restrict__ Vf)
{
    const long idx = (long)blockIdx.x * 256 + threadIdx.x;
    const int  i   = (int)(idx & 63);
    const int  h   = (int)((idx >> 6) & 15);
    const long bl  = idx >> 10;
    const long l   = bl & 2047;
    const long b   = bl >> 11;

    float freq = expf(-(float)i * 0.14391156642875464f);
    float angle = (float)l * freq;
    float s, c;
    sincosf(angle, &s, &c);

    const __half* qp = qkv + bl * (3 * DMODEL) + h * HD + i;
    const __half* kp = qp + DMODEL;
    const __half* vp = qp + 2 * DMODEL;
    float q1 = __half2float(qp[0]), q2 = __half2float(qp[64]);
    float k1 = __half2float(kp[0]), k2 = __half2float(kp[64]);

    const float scale = 0.088388347648318447f;  // 1/sqrt(128)
    size_t base = ((size_t)(b * NH + h) * LSEQ + l) * HD + i;
    Qf[base]      = __float2half_rn((q1 * c - q2 * s) * scale);
    Qf[base + 64] = __float2half_rn((q2 * c + q1 * s) * scale);
    Kf[base]      = __float2half_rn(k1 * c - k2 * s);
    Kf[base + 64] = __float2half_rn(k2 * c + k1 * s);
    Vf[base]      = vp[0];
    Vf[base + 64] = vp[64];
}

// ---------------------------------------------------------------------------
// Flash attention v2 (fp16 mma, causal) with double-buffered K/V pipeline.
// CTA = 64 q-rows, 4 warps. smem: Q + 2x(K,V) = 5 tiles (87KB) -> 2 CTAs/SM.
// ---------------------------------------------------------------------------
#define FA_PITCH 272
#define FA_TILE  (64 * FA_PITCH)     // 17408
#define FA_SMEM  (5 * FA_TILE)       // 87040

__global__ void __launch_bounds__(128)
attn_mma(const __half* __restrict__ Qf, const __half* __restrict__ Kf,
         const __half* __restrict__ Vf, __half* __restrict__ O)
{
    extern __shared__ __align__(16) char fsm[];
    const uint32_t sQ  = smem_u32(fsm);
    const uint32_t sKV = sQ + FA_TILE;   // buf b: K at sKV + b*2*FA_TILE, V at +FA_TILE
    const int tid  = threadIdx.x;
    const int lane = tid & 31;
    const int w    = tid >> 5;
    const int bh   = blockIdx.y;
    const int qi   = gridDim.x - 1 - blockIdx.x;
    const int q0   = qi * 64;

    const __half* qb = Qf + (size_t)bh * LSEQ * HD;
    const __half* kb = Kf + (size_t)bh * LSEQ * HD;
    const __half* vb = Vf + (size_t)bh * LSEQ * HD;

    // Q load (group 0)
    #pragma unroll
    for (int i = 0; i < 8; i++) {
        int e = tid + i * 128;
        int r = e >> 4, cc = e & 15;
        cp16(sQ + r * FA_PITCH + cc * 16, qb + (size_t)(q0 + r) * HD + cc * 8);
    }
    asm volatile("cp.async.commit_group;" ::: "memory");

    // tile 0 K/V load (group 1)
    #pragma unroll
    for (int i = 0; i < 8; i++) {
        int e = tid + i * 128;
        int r = e >> 4, cc = e & 15;
        size_t go = (size_t)r * HD + cc * 8;
        cp16(sKV + r * FA_PITCH + cc * 16,           kb + go);
        cp16(sKV + FA_TILE + r * FA_PITCH + cc * 16, vb + go);
    }
    asm volatile("cp.async.commit_group;" ::: "memory");

    const int qg0 = q0 + w * 16 + (lane >> 2);
    const int qg1 = qg0 + 8;

    const uint32_t a_off = (uint32_t)((w * 16 + (lane & 7) + ((lane >> 3) & 1) * 8) * FA_PITCH
                                      + (lane >> 4) * 16);
    const uint32_t b_off = (uint32_t)((lane & 7) * FA_PITCH + ((lane >> 3) & 1) * 16);
    const uint32_t v_off = (uint32_t)((lane & 15) * FA_PITCH);

    float oacc[16][4];
    #pragma unroll
    for (int i = 0; i < 16; i++)
        #pragma unroll
        for (int q = 0; q < 4; q++) oacc[i][q] = 0.f;
    float m0 = -1e30f, m1 = -1e30f, l0 = 0.f, l1 = 0.f;

    const int nk = qi + 1;
    for (int kt = 0; kt < nk; kt++) {
        // prefetch tile kt+1 into the other buffer (read last in iter kt-1)
        if (kt + 1 < nk) {
            const uint32_t dst = sKV + (uint32_t)((kt + 1) & 1) * (2 * FA_TILE);
            const int kn0 = (kt + 1) * 64;
            #pragma unroll
            for (int i = 0; i < 8; i++) {
                int e = tid + i * 128;
                int r = e >> 4, cc = e & 15;
                size_t go = (size_t)(kn0 + r) * HD + cc * 8;
                cp16(dst + r * FA_PITCH + cc * 16,           kb + go);
                cp16(dst + FA_TILE + r * FA_PITCH + cc * 16, vb + go);
            }
            asm volatile("cp.async.commit_group;" ::: "memory");
            asm volatile("cp.async.wait_group 1;" ::: "memory");
        } else {
            asm volatile("cp.async.wait_group 0;" ::: "memory");
        }
        __syncthreads();

        const uint32_t sK = sKV + (uint32_t)(kt & 1) * (2 * FA_TILE);
        const uint32_t sV = sK + FA_TILE;
        const int k0 = kt * 64;

        float sacc[8][4];
        #pragma unroll
        for (int nt = 0; nt < 8; nt++)
            #pragma unroll
            for (int q = 0; q < 4; q++) sacc[nt][q] = 0.f;

        #pragma unroll
        for (int ks = 0; ks < 8; ks++) {
            uint32_t aq[4];
            ldsm_x4(aq, sQ + a_off + ks * 32);
            #pragma unroll
            for (int nt = 0; nt < 8; nt++) {
                uint32_t bk[2];
                ldsm_x2(bk, sK + nt * (8 * FA_PITCH) + b_off + ks * 32);
                mma_f32(sacc[nt], aq, bk);
            }
        }

        if (kt == qi) {
            #pragma unroll
            for (int nt = 0; nt < 8; nt++) {
                int jg = k0 + nt * 8 + (lane & 3) * 2;
                if (jg > qg0)     sacc[nt][0] = -1e30f;
                if (jg + 1 > qg0) sacc[nt][1] = -1e30f;
                if (jg > qg1)     sacc[nt][2] = -1e30f;
                if (jg + 1 > qg1) sacc[nt][3] = -1e30f;
            }
        }

        float tm0 = -1e30f, tm1 = -1e30f;
        #pragma unroll
        for (int nt = 0; nt < 8; nt++) {
            tm0 = fmaxf(tm0, fmaxf(sacc[nt][0], sacc[nt][1]));
            tm1 = fmaxf(tm1, fmaxf(sacc[nt][2], sacc[nt][3]));
        }
        tm0 = fmaxf(tm0, __shfl_xor_sync(0xffffffffu, tm0, 1));
        tm0 = fmaxf(tm0, __shfl_xor_sync(0xffffffffu, tm0, 2));
        tm1 = fmaxf(tm1, __shfl_xor_sync(0xffffffffu, tm1, 1));
        tm1 = fmaxf(tm1, __shfl_xor_sync(0xffffffffu, tm1, 2));

        float mn0 = fmaxf(m0, tm0), mn1 = fmaxf(m1, tm1);
        float c0 = __expf(m0 - mn0), c1 = __expf(m1 - mn1);
        float ps0 = 0.f, ps1 = 0.f;
        #pragma unroll
        for (int nt = 0; nt < 8; nt++) {
            sacc[nt][0] = __expf(sacc[nt][0] - mn0);
            sacc[nt][1] = __expf(sacc[nt][1] - mn0);
            sacc[nt][2] = __expf(sacc[nt][2] - mn1);
            sacc[nt][3] = __expf(sacc[nt][3] - mn1);
            ps0 += sacc[nt][0] + sacc[nt][1];
            ps1 += sacc[nt][2] + sacc[nt][3];
        }
        ps0 += __shfl_xor_sync(0xffffffffu, ps0, 1);
        ps0 += __shfl_xor_sync(0xffffffffu, ps0, 2);
        ps1 += __shfl_xor_sync(0xffffffffu, ps1, 1);
        ps1 += __shfl_xor_sync(0xffffffffu, ps1, 2);
        l0 = l0 * c0 + ps0;  m0 = mn0;
        l1 = l1 * c1 + ps1;  m1 = mn1;
        #pragma unroll
        for (int nt2 = 0; nt2 < 16; nt2++) {
            oacc[nt2][0] *= c0;  oacc[nt2][1] *= c0;
            oacc[nt2][2] *= c1;  oacc[nt2][3] *= c1;
        }

        uint32_t pa[4][4];
        #pragma unroll
        for (int kp = 0; kp < 4; kp++) {
            pa[kp][0] = pack2h(sacc[2*kp][0],   sacc[2*kp][1]);
            pa[kp][1] = pack2h(sacc[2*kp][2],   sacc[2*kp][3]);
            pa[kp][2] = pack2h(sacc[2*kp+1][0], sacc[2*kp+1][1]);
            pa[kp][3] = pack2h(sacc[2*kp+1][2], sacc[2*kp+1][3]);
        }

        #pragma unroll
        for (int kp = 0; kp < 4; kp++) {
            const uint32_t vb_ = sV + (uint32_t)(kp * 16) * FA_PITCH + v_off;
            #pragma unroll
            for (int nt2 = 0; nt2 < 16; nt2++) {
                uint32_t bv[2];
                ldsm_x2t(bv, vb_ + nt2 * 16);
                mma_f32(oacc[nt2], pa[kp], bv);
            }
        }
        __syncthreads();   // all warps done reading buf[kt&1] before its reuse
    }

    float i0 = 1.f / l0, i1 = 1.f / l1;
    const int b  = bh >> 4;
    const int hh = bh & 15;
    size_t row0 = (size_t)b * LSEQ + qg0;
    size_t row1 = row0 + 8;
    #pragma unroll
    for (int nt2 = 0; nt2 < 16; nt2++) {
        int col = hh * HD + nt2 * 8 + (lane & 3) * 2;
        __half2 h0, h1;
        h0.x = __float2half_rn(oacc[nt2][0] * i0);
        h0.y = __float2half_rn(oacc[nt2][1] * i0);
        h1.x = __float2half_rn(oacc[nt2][2] * i1);
        h1.y = __float2half_rn(oacc[nt2][3] * i1);
        *(__half2*)(O + row0 * DMODEL + col) = h0;
        *(__half2*)(O + row1 * DMODEL + col) = h1;
    }
}

// ---------------------------------------------------------------------------
// Host launcher
// ---------------------------------------------------------------------------
extern "C" void kernel_launch(void* const* d_in, const int* in_sizes, int n_in,
                              void* d_out, int out_size)
{
    const float* x    = (const float*)d_in[0];
    const float* Wqkv = (const float*)d_in[1];
    const float* bqkv = (const float*)d_in[2];
    const float* Wo   = (const float*)d_in[3];
    const float* bo   = (const float*)d_in[4];
    const float* g1   = (const float*)d_in[5];
    const float* g2   = (const float*)d_in[6];
    const float* Wp   = (const float*)d_in[7];
    const float* bp   = (const float*)d_in[8];
    const float* Wff  = (const float*)d_in[9];
    const float* bff  = (const float*)d_in[10];
    float* out = (float*)d_out;

    float *p_x2;
    __half *p_qkvh, *p_xn, *p_o, *p_ff, *p_qf, *p_kf, *p_vf;
    __half *p_wqkv, *p_wo, *p_wp, *p_wff;
    cudaGetSymbolAddress((void**)&p_x2,   g_x2);
    cudaGetSymbolAddress((void**)&p_qkvh, g_qkvh);
    cudaGetSymbolAddress((void**)&p_xn,   g_xn);
    cudaGetSymbolAddress((void**)&p_o,    g_o);
    cudaGetSymbolAddress((void**)&p_ff,   g_ff);
    cudaGetSymbolAddress((void**)&p_qf,   g_qf);
    cudaGetSymbolAddress((void**)&p_kf,   g_kf);
    cudaGetSymbolAddress((void**)&p_vf,   g_vf);
    cudaGetSymbolAddress((void**)&p_wqkv, g_wqkv);
    cudaGetSymbolAddress((void**)&p_wo,   g_wo);
    cudaGetSymbolAddress((void**)&p_wp,   g_wp);
    cudaGetSymbolAddress((void**)&p_wff,  g_wff);

    cudaFuncSetAttribute(attn_mma,          cudaFuncAttributeMaxDynamicSharedMemorySize, FA_SMEM);
    cudaFuncSetAttribute(gemm_kernel<0>,    cudaFuncAttributeMaxDynamicSharedMemorySize, GSMEM);
    cudaFuncSetAttribute(gemm_kernel<1>,    cudaFuncAttributeMaxDynamicSharedMemorySize, GSMEM);
    cudaFuncSetAttribute(gemm_ffn_kernel,   cudaFuncAttributeMaxDynamicSharedMemorySize, FGSMEM);

    // Weight transposition (fp16)
    transp_half<<<dim3(3 * DMODEL / 32, DMODEL / 32), 256>>>(Wqkv, p_wqkv, DMODEL, 3 * DMODEL);
    transp_half<<<dim3(DMODEL / 32, DMODEL / 32), 256>>>(Wo, p_wo, DMODEL, DMODEL);
    transp_half<<<dim3(8 * DMODEL / 32, DMODEL / 32), 256>>>(Wp, p_wp, DMODEL, 8 * DMODEL);
    transp_half<<<dim3(DMODEL / 32, 4 * DMODEL / 32), 256>>>(Wff, p_wff, 4 * DMODEL, DMODEL);

    // 1. pre-norm (-> fp16)
    rmsnorm_half<<<ROWS, 256>>>(x, g1, p_xn);

    // 2. QKV projection (fp16 out)
    gemm_kernel<1><<<dim3(3 * DMODEL / 128, ROWS / 128), 512, GSMEM>>>(
        p_xn, p_wqkv, bqkv, nullptr, p_qkvh, DMODEL, 3 * DMODEL);

    // 3. RoPE + split to fp16 Q(scaled)/K/V per-head buffers
    rope_split_kernel<<<(ROWS * NH * 64) / 256, 256>>>(p_qkvh, p_qf, p_kf, p_vf);

    // 4. causal flash attention (fp16 mma, pipelined) -> fp16 O
    attn_mma<<<dim3(LSEQ / 64, BD * NH), 128, FA_SMEM>>>(p_qf, p_kf, p_vf, p_o);

    // 5. output projection + residual (fp32 out)
    gemm_kernel<0><<<dim3(DMODEL / 128, ROWS / 128), 512, GSMEM>>>(
        p_o, p_wo, bo, x, p_x2, DMODEL, DMODEL);

    // 6. second pre-norm (-> fp16)
    rmsnorm_half<<<ROWS, 256>>>(p_x2, g2, p_xn);

    // 7+8. FFN up-projection fused with SwiGLU (-> fp16 ff)
    gemm_ffn_kernel<<<dim3(4 * DMODEL / 128, ROWS / 128), 512, FGSMEM>>>(
        p_xn, p_wp, bp, p_ff, DMODEL);

    // 9. FFN down-projection + residual -> output (fp32)
    gemm_kernel<0><<<dim3(DMODEL / 128, ROWS / 128), 512, GSMEM>>>(
        p_ff, p_wff, bff, p_x2, out, 4 * DMODEL, DMODEL);
}

// round 16
// speedup vs baseline: 3.7105x; 1.0839x over previous
#include <cuda_runtime.h>
#include <cuda_fp16.h>
#include <math.h>
#include <stdint.h>

// ---------------------------------------------------------------------------
// Problem constants
// ---------------------------------------------------------------------------
#define BD      2
#define LSEQ    2048
#define DMODEL  2048
#define NH      16
#define HD      128
#define ROWS    (BD * LSEQ)      // 4096

// ---------------------------------------------------------------------------
// Scratch (device globals -- no allocation allowed)
// ---------------------------------------------------------------------------
__device__ float  g_x2 [ROWS * DMODEL];

__device__ __half g_qkvh[ROWS * 3 * DMODEL];   // fp16 QKV
__device__ __half g_xn [ROWS * DMODEL];
__device__ __half g_o  [ROWS * DMODEL];
__device__ __half g_ff [(size_t)ROWS * 4 * DMODEL];
__device__ __half g_qf [ROWS * DMODEL];   // [bh][L][HD], q pre-scaled + roped
__device__ __half g_kf [ROWS * DMODEL];   // [bh][L][HD], roped
__device__ __half g_vf [ROWS * DMODEL];   // [bh][L][HD]
// transposed weights [N, K] fp16
__device__ __half g_wqkv[3 * DMODEL * DMODEL];
__device__ __half g_wo  [DMODEL * DMODEL];
__device__ __half g_wp  [(size_t)8 * DMODEL * DMODEL];
__device__ __half g_wff [(size_t)4 * DMODEL * DMODEL];

// ---------------------------------------------------------------------------
// Helpers
// ---------------------------------------------------------------------------
__device__ __forceinline__ uint32_t smem_u32(const void* p) {
    uint32_t a;
    asm("{ .reg .u64 t; cvta.to.shared.u64 t, %1; cvt.u32.u64 %0, t; }"
        : "=r"(a) : "l"(p));
    return a;
}
__device__ __forceinline__ void cp16(uint32_t dst, const void* src) {
    asm volatile("cp.async.cg.shared.global [%0], [%1], 16;" :: "r"(dst), "l"(src));
}
__device__ __forceinline__ void ldsm_x4(uint32_t* r, uint32_t a) {
    asm volatile("ldmatrix.sync.aligned.m8n8.x4.shared.b16 {%0,%1,%2,%3}, [%4];"
        : "=r"(r[0]), "=r"(r[1]), "=r"(r[2]), "=r"(r[3]) : "r"(a));
}
__device__ __forceinline__ void ldsm_x2(uint32_t* r, uint32_t a) {
    asm volatile("ldmatrix.sync.aligned.m8n8.x2.shared.b16 {%0,%1}, [%2];"
        : "=r"(r[0]), "=r"(r[1]) : "r"(a));
}
__device__ __forceinline__ void ldsm_x2t(uint32_t* r, uint32_t a) {
    asm volatile("ldmatrix.sync.aligned.m8n8.x2.trans.shared.b16 {%0,%1}, [%2];"
        : "=r"(r[0]), "=r"(r[1]) : "r"(a));
}
__device__ __forceinline__ void mma_f32(float* d, const uint32_t* a, const uint32_t* b) {
    asm volatile("mma.sync.aligned.m16n8k16.row.col.f32.f16.f16.f32 "
        "{%0,%1,%2,%3}, {%4,%5,%6,%7}, {%8,%9}, {%0,%1,%2,%3};"
        : "+f"(d[0]), "+f"(d[1]), "+f"(d[2]), "+f"(d[3])
        : "r"(a[0]), "r"(a[1]), "r"(a[2]), "r"(a[3]), "r"(b[0]), "r"(b[1]));
}
__device__ __forceinline__ uint32_t pack2h(float a, float b) {
    __half2 h = __floats2half2_rn(a, b);
    return *(uint32_t*)&h;
}
__device__ __forceinline__ float silu_f(float x) {
    return x / (1.f + __expf(-x));
}

// ---------------------------------------------------------------------------
// fp16 mma GEMM: C[M,N] = A[M,K] @ B[N,K]^T + bias (+res)
// OUTH=0: fp32 C (+ optional fp32 res). OUTH=1: fp16 C, no res.
// CTA 128x128, 16 warps, warp tile 32x32, 512 threads, K-chunk 64,
// 4-stage cp.async (144KB smem). Pitch 144B: ldmatrix conflict-free
// (row byte offsets r*144 mod 128 hit 8 distinct 16B segments).
// ---------------------------------------------------------------------------
#define GK       64
#define APITCH_B 144
#define COMP_B   18432            // 128 * 144
#define STAGE_B  36864            // A + B
#define NSTAGE   4
#define GSMEM    (NSTAGE * STAGE_B)   // 147456

__device__ __forceinline__ void g_load_chunk(
    uint32_t st, int c, int tid,
    const __half* __restrict__ A, const __half* __restrict__ B,
    int K, int m0, int n0)
{
    const int k0 = c * GK;
    #pragma unroll
    for (int i = 0; i < 2; i++) {
        int e = tid + (i << 9);          // 0..1023
        int r = e >> 3, cc = e & 7;      // row, 16B chunk in 128B row
        uint32_t so = (uint32_t)(r * APITCH_B + cc * 16);
        cp16(st + so,          A + (size_t)(m0 + r) * K + k0 + cc * 8);
        cp16(st + COMP_B + so, B + (size_t)(n0 + r) * K + k0 + cc * 8);
    }
    asm volatile("cp.async.commit_group;" ::: "memory");
}

template<int OUTH>
__global__ void __launch_bounds__(512)
gemm_kernel(const __half* __restrict__ A, const __half* __restrict__ B,
            const float* __restrict__ bias, const float* __restrict__ res,
            void* __restrict__ Cv, int K, int N)
{
    extern __shared__ __align__(16) char sm_[];
    const uint32_t sb = smem_u32(sm_);
    const int tid  = threadIdx.x;
    const int lane = tid & 31;
    const int wid  = tid >> 5;
    const int wm   = wid >> 2;
    const int wn   = wid & 3;
    const int m0 = blockIdx.y << 7;
    const int n0 = blockIdx.x << 7;
    const int NC = K / GK;

    float acc[2][4][4];
    #pragma unroll
    for (int i = 0; i < 2; i++)
        #pragma unroll
        for (int j = 0; j < 4; j++)
            #pragma unroll
            for (int q = 0; q < 4; q++) acc[i][j][q] = 0.f;

    g_load_chunk(sb,               0, tid, A, B, K, m0, n0);
    g_load_chunk(sb + STAGE_B,     1, tid, A, B, K, m0, n0);
    g_load_chunk(sb + 2 * STAGE_B, 2, tid, A, B, K, m0, n0);

    const int rowA  = (lane & 7) + ((lane >> 3) & 1) * 8;
    const int kaddA = (lane >> 4) * 16;
    const uint32_t a_ld = (uint32_t)((wm * 32 + rowA) * APITCH_B + kaddA);
    const int rowB  = lane & 7;
    const int kaddB = ((lane >> 3) & 1) * 16;
    const uint32_t b_ld = (uint32_t)((wn * 32 + rowB) * APITCH_B + kaddB);

    for (int c = 0; c < NC; c++) {
        asm volatile("cp.async.wait_group 2;" ::: "memory");
        __syncthreads();

        if (c + 3 < NC)
            g_load_chunk(sb + (uint32_t)((c + 3) & 3) * STAGE_B, c + 3, tid,
                         A, B, K, m0, n0);

        const uint32_t st = sb + (uint32_t)(c & 3) * STAGE_B;

        #pragma unroll
        for (int kh = 0; kh < 4; kh++) {
            const uint32_t abase = st + a_ld + kh * 32;
            const uint32_t bbase = st + COMP_B + b_ld + kh * 32;

            uint32_t ar[2][4], br[4][2];
            #pragma unroll
            for (int mt = 0; mt < 2; mt++)
                ldsm_x4(ar[mt], abase + mt * (16 * APITCH_B));
            #pragma unroll
            for (int nt = 0; nt < 4; nt++)
                ldsm_x2(br[nt], bbase + nt * (8 * APITCH_B));

            #pragma unroll
            for (int mt = 0; mt < 2; mt++)
                #pragma unroll
                for (int nt = 0; nt < 4; nt++)
                    mma_f32(acc[mt][nt], ar[mt], br[nt]);
        }
    }

    #pragma unroll
    for (int mt = 0; mt < 2; mt++) {
        #pragma unroll
        for (int nt = 0; nt < 4; nt++) {
            const int rg = m0 + wm * 32 + mt * 16 + (lane >> 2);
            const int cg = n0 + wn * 32 + nt * 8 + (lane & 3) * 2;
            float2 bv = *(const float2*)(bias + cg);
            float2 o0, o1;
            o0.x = acc[mt][nt][0] + bv.x;  o0.y = acc[mt][nt][1] + bv.y;
            o1.x = acc[mt][nt][2] + bv.x;  o1.y = acc[mt][nt][3] + bv.y;
            if (OUTH) {
                __half* C = (__half*)Cv;
                __half2 h0, h1;
                h0.x = __float2half_rn(o0.x);  h0.y = __float2half_rn(o0.y);
                h1.x = __float2half_rn(o1.x);  h1.y = __float2half_rn(o1.y);
                *(__half2*)(C + (size_t)rg * N + cg)       = h0;
                *(__half2*)(C + (size_t)(rg + 8) * N + cg) = h1;
            } else {
                float* C = (float*)Cv;
                if (res) {
                    float2 r0 = *(const float2*)(res + (size_t)rg * N + cg);
                    float2 r1 = *(const float2*)(res + (size_t)(rg + 8) * N + cg);
                    o0.x += r0.x; o0.y += r0.y;
                    o1.x += r1.x; o1.y += r1.y;
                }
                *(float2*)(C + (size_t)rg * N + cg)       = o0;
                *(float2*)(C + (size_t)(rg + 8) * N + cg) = o1;
            }
        }
    }
}

// ---------------------------------------------------------------------------
// Fused FFN-up GEMM + SwiGLU, K-chunk 64. smem/stage: A+Bg+Bv = 55296;
// 4 stages = 221184 bytes.
// ---------------------------------------------------------------------------
#define FSTAGE_B (3 * COMP_B)          // 55296
#define FGSMEM   (NSTAGE * FSTAGE_B)   // 221184

__device__ __forceinline__ void f_load_chunk(
    uint32_t st, int c, int tid,
    const __half* __restrict__ A, const __half* __restrict__ Bg,
    const __half* __restrict__ Bv, int K, int m0, int n0)
{
    const int k0 = c * GK;
    #pragma unroll
    for (int i = 0; i < 2; i++) {
        int e = tid + (i << 9);
        int r = e >> 3, cc = e & 7;
        uint32_t so = (uint32_t)(r * APITCH_B + cc * 16);
        size_t goA = (size_t)(m0 + r) * K + k0 + cc * 8;
        size_t goB = (size_t)(n0 + r) * K + k0 + cc * 8;
        cp16(st + so,              A  + goA);
        cp16(st + COMP_B + so,     Bg + goB);
        cp16(st + 2 * COMP_B + so, Bv + goB);
    }
    asm volatile("cp.async.commit_group;" ::: "memory");
}

__global__ void __launch_bounds__(512)
gemm_ffn_kernel(const __half* __restrict__ A, const __half* __restrict__ Wp,
                const float* __restrict__ bp, __half* __restrict__ FF, int K)
{
    extern __shared__ __align__(16) char sm_[];
    const uint32_t sb = smem_u32(sm_);
    const int tid  = threadIdx.x;
    const int lane = tid & 31;
    const int wid  = tid >> 5;
    const int wm   = wid >> 2;
    const int wn   = wid & 3;
    const int m0 = blockIdx.y << 7;
    const int n0 = blockIdx.x << 7;
    const int NC = K / GK;

    const __half* Bg = Wp;
    const __half* Bv = Wp + (size_t)8192 * K;

    float accg[2][4][4], accv[2][4][4];
    #pragma unroll
    for (int i = 0; i < 2; i++)
        #pragma unroll
        for (int j = 0; j < 4; j++)
            #pragma unroll
            for (int q = 0; q < 4; q++) { accg[i][j][q] = 0.f; accv[i][j][q] = 0.f; }

    f_load_chunk(sb,                0, tid, A, Bg, Bv, K, m0, n0);
    f_load_chunk(sb + FSTAGE_B,     1, tid, A, Bg, Bv, K, m0, n0);
    f_load_chunk(sb + 2 * FSTAGE_B, 2, tid, A, Bg, Bv, K, m0, n0);

    const int rowA  = (lane & 7) + ((lane >> 3) & 1) * 8;
    const int kaddA = (lane >> 4) * 16;
    const uint32_t a_ld = (uint32_t)((wm * 32 + rowA) * APITCH_B + kaddA);
    const int rowB  = lane & 7;
    const int kaddB = ((lane >> 3) & 1) * 16;
    const uint32_t b_ld = (uint32_t)((wn * 32 + rowB) * APITCH_B + kaddB);

    for (int c = 0; c < NC; c++) {
        asm volatile("cp.async.wait_group 2;" ::: "memory");
        __syncthreads();

        if (c + 3 < NC)
            f_load_chunk(sb + (uint32_t)((c + 3) & 3) * FSTAGE_B, c + 3, tid,
                         A, Bg, Bv, K, m0, n0);

        const uint32_t st = sb + (uint32_t)(c & 3) * FSTAGE_B;

        #pragma unroll
        for (int kh = 0; kh < 4; kh++) {
            const uint32_t abase = st + a_ld + kh * 32;
            const uint32_t gbase = st + COMP_B + b_ld + kh * 32;
            const uint32_t vbase = st + 2 * COMP_B + b_ld + kh * 32;

            uint32_t ar[2][4];
            #pragma unroll
            for (int mt = 0; mt < 2; mt++)
                ldsm_x4(ar[mt], abase + mt * (16 * APITCH_B));

            #pragma unroll
            for (int nt = 0; nt < 4; nt++) {
                uint32_t bg[2], bv_[2];
                ldsm_x2(bg,  gbase + nt * (8 * APITCH_B));
                ldsm_x2(bv_, vbase + nt * (8 * APITCH_B));
                #pragma unroll
                for (int mt = 0; mt < 2; mt++) {
                    mma_f32(accg[mt][nt], ar[mt], bg);
                    mma_f32(accv[mt][nt], ar[mt], bv_);
                }
            }
        }
    }

    #pragma unroll
    for (int mt = 0; mt < 2; mt++) {
        #pragma unroll
        for (int nt = 0; nt < 4; nt++) {
            const int rg = m0 + wm * 32 + mt * 16 + (lane >> 2);
            const int cg = n0 + wn * 32 + nt * 8 + (lane & 3) * 2;
            float2 bg2 = *(const float2*)(bp + cg);
            float2 bv2 = *(const float2*)(bp + 8192 + cg);
            float f00 = silu_f(accg[mt][nt][0] + bg2.x) * (accv[mt][nt][0] + bv2.x);
            float f01 = silu_f(accg[mt][nt][1] + bg2.y) * (accv[mt][nt][1] + bv2.y);
            float f10 = silu_f(accg[mt][nt][2] + bg2.x) * (accv[mt][nt][2] + bv2.x);
            float f11 = silu_f(accg[mt][nt][3] + bg2.y) * (accv[mt][nt][3] + bv2.y);
            __half2 h0, h1;
            h0.x = __float2half_rn(f00);  h0.y = __float2half_rn(f01);
            h1.x = __float2half_rn(f10);  h1.y = __float2half_rn(f11);
            *(__half2*)(FF + (size_t)rg * 8192 + cg)       = h0;
            *(__half2*)(FF + (size_t)(rg + 8) * 8192 + cg) = h1;
        }
    }
}

// ---------------------------------------------------------------------------
// Weight transpose + fp16 round
// ---------------------------------------------------------------------------
__global__ void __launch_bounds__(256)
transp_half(const float* __restrict__ W, __half* __restrict__ Th, int Kd, int Nd)
{
    __shared__ float t[32][33];
    const int n0 = blockIdx.x * 32, k0 = blockIdx.y * 32;
    const int tx = threadIdx.x & 31, ty = threadIdx.x >> 5;
    #pragma unroll
    for (int i = 0; i < 4; i++) {
        int kk = ty + i * 8;
        t[kk][tx] = W[(size_t)(k0 + kk) * Nd + n0 + tx];
    }
    __syncthreads();
    #pragma unroll
    for (int i = 0; i < 4; i++) {
        int nn = ty + i * 8;
        Th[(size_t)(n0 + nn) * Kd + k0 + tx] = __float2half_rn(t[tx][nn]);
    }
}

// ---------------------------------------------------------------------------
// RMSNorm -> fp16
// ---------------------------------------------------------------------------
__global__ void __launch_bounds__(256)
rmsnorm_half(const float* __restrict__ in, const float* __restrict__ g,
             __half* __restrict__ outh)
{
    __shared__ float red[8];
    const int row = blockIdx.x;
    const int tid = threadIdx.x;
    const float4* inr = (const float4*)(in + (size_t)row * DMODEL);
    float4 v0 = inr[tid];
    float4 v1 = inr[tid + 256];
    float ss = v0.x*v0.x + v0.y*v0.y + v0.z*v0.z + v0.w*v0.w
             + v1.x*v1.x + v1.y*v1.y + v1.z*v1.z + v1.w*v1.w;
    #pragma unroll
    for (int o = 16; o; o >>= 1) ss += __shfl_xor_sync(0xffffffffu, ss, o);
    if ((tid & 31) == 0) red[tid >> 5] = ss;
    __syncthreads();
    float tot = red[0]+red[1]+red[2]+red[3]+red[4]+red[5]+red[6]+red[7];
    float rs = rsqrtf(tot * (1.0f / DMODEL) + 1e-8f);

    const float4* gr = (const float4*)g;
    float4 ga = gr[tid], gb = gr[tid + 256];
    __half2* oh2 = (__half2*)(outh + (size_t)row * DMODEL);
    float y[8] = { v0.x*rs*ga.x, v0.y*rs*ga.y, v0.z*rs*ga.z, v0.w*rs*ga.w,
                   v1.x*rs*gb.x, v1.y*rs*gb.y, v1.z*rs*gb.z, v1.w*rs*gb.w };
    #pragma unroll
    for (int p = 0; p < 4; p++) {
        __half2 hh;
        hh.x = __float2half_rn(y[p*2]);
        hh.y = __float2half_rn(y[p*2+1]);
        int base = (p < 2) ? (tid*2 + p) : ((tid+256)*2 + (p-2));
        oh2[base] = hh;
    }
}

// ---------------------------------------------------------------------------
// RoPE (fp16 in) + split into [bh][L][HD] Q(scaled)/K/V buffers
// ---------------------------------------------------------------------------
__global__ void __launch_bounds__(256)
rope_split_kernel(const __half* __restrict__ qkv,
                  __half* __restrict__ Qf, __half* __restrict__ Kf,
                  __half* __restrict__ Vf)
{
    const long idx = (long)blockIdx.x * 256 + threadIdx.x;
    const int  i   = (int)(idx & 63);
    const int  h   = (int)((idx >> 6) & 15);
    const long bl  = idx >> 10;
    const long l   = bl & 2047;
    const long b   = bl >> 11;

    float freq = expf(-(float)i * 0.14391156642875464f);
    float angle = (float)l * freq;
    float s, c;
    sincosf(angle, &s, &c);

    const __half* qp = qkv + bl * (3 * DMODEL) + h * HD + i;
    const __half* kp = qp + DMODEL;
    const __half* vp = qp + 2 * DMODEL;
    float q1 = __half2float(qp[0]), q2 = __half2float(qp[64]);
    float k1 = __half2float(kp[0]), k2 = __half2float(kp[64]);

    const float scale = 0.088388347648318447f;  // 1/sqrt(128)
    size_t base = ((size_t)(b * NH + h) * LSEQ + l) * HD + i;
    Qf[base]      = __float2half_rn((q1 * c - q2 * s) * scale);
    Qf[base + 64] = __float2half_rn((q2 * c + q1 * s) * scale);
    Kf[base]      = __float2half_rn(k1 * c - k2 * s);
    Kf[base + 64] = __float2half_rn(k2 * c + k1 * s);
    Vf[base]      = vp[0];
    Vf[base + 64] = vp[64];
}

// ---------------------------------------------------------------------------
// Flash attention v2 (fp16 mma, causal), Q-tile 128 rows, 8 warps (256 thr),
// warp tile 16 q-rows x 64 kv. Double-buffered K/V pipeline.
// smem: Q 128x272 + 2x(K,V) 64x272 = 104448 B.
// ---------------------------------------------------------------------------
#define FA_PITCH 272
#define FAQ_TILE (128 * FA_PITCH)    // 34816
#define FAK_TILE (64 * FA_PITCH)     // 17408
#define FA_SMEM  (FAQ_TILE + 4 * FAK_TILE)  // 104448

__global__ void __launch_bounds__(256)
attn_mma(const __half* __restrict__ Qf, const __half* __restrict__ Kf,
         const __half* __restrict__ Vf, __half* __restrict__ O)
{
    extern __shared__ __align__(16) char fsm[];
    const uint32_t sQ  = smem_u32(fsm);
    const uint32_t sKV = sQ + FAQ_TILE;  // buf b: K at sKV + b*2*FAK_TILE, V at +FAK_TILE
    const int tid  = threadIdx.x;
    const int lane = tid & 31;
    const int w    = tid >> 5;           // 0..7
    const int bh   = blockIdx.y;
    const int qi   = gridDim.x - 1 - blockIdx.x;   // heavy tiles first
    const int q0   = qi * 128;

    const __half* qb = Qf + (size_t)bh * LSEQ * HD;
    const __half* kb = Kf + (size_t)bh * LSEQ * HD;
    const __half* vb = Vf + (size_t)bh * LSEQ * HD;

    // Q load (128 rows x 16 chunks = 2048 cp16; 8 per thread)
    #pragma unroll
    for (int i = 0; i < 8; i++) {
        int e = tid + i * 256;
        int r = e >> 4, cc = e & 15;
        cp16(sQ + r * FA_PITCH + cc * 16, qb + (size_t)(q0 + r) * HD + cc * 8);
    }
    asm volatile("cp.async.commit_group;" ::: "memory");

    // tile 0 K/V load
    #pragma unroll
    for (int i = 0; i < 4; i++) {
        int e = tid + i * 256;
        int r = e >> 4, cc = e & 15;
        size_t go = (size_t)r * HD + cc * 8;
        cp16(sKV + r * FA_PITCH + cc * 16,            kb + go);
        cp16(sKV + FAK_TILE + r * FA_PITCH + cc * 16, vb + go);
    }
    asm volatile("cp.async.commit_group;" ::: "memory");

    const int qg0 = q0 + w * 16 + (lane >> 2);
    const int qg1 = qg0 + 8;

    const uint32_t a_off = (uint32_t)((w * 16 + (lane & 7) + ((lane >> 3) & 1) * 8) * FA_PITCH
                                      + (lane >> 4) * 16);
    const uint32_t b_off = (uint32_t)((lane & 7) * FA_PITCH + ((lane >> 3) & 1) * 16);
    const uint32_t v_off = (uint32_t)((lane & 15) * FA_PITCH);

    float oacc[16][4];
    #pragma unroll
    for (int i = 0; i < 16; i++)
        #pragma unroll
        for (int q = 0; q < 4; q++) oacc[i][q] = 0.f;
    float m0 = -1e30f, m1 = -1e30f, l0 = 0.f, l1 = 0.f;

    const int nk = 2 * qi + 2;   // k tiles of 64 covering [0, q0+128)
    for (int kt = 0; kt < nk; kt++) {
        if (kt + 1 < nk) {
            const uint32_t dst = sKV + (uint32_t)((kt + 1) & 1) * (2 * FAK_TILE);
            const int kn0 = (kt + 1) * 64;
            #pragma unroll
            for (int i = 0; i < 4; i++) {
                int e = tid + i * 256;
                int r = e >> 4, cc = e & 15;
                size_t go = (size_t)(kn0 + r) * HD + cc * 8;
                cp16(dst + r * FA_PITCH + cc * 16,            kb + go);
                cp16(dst + FAK_TILE + r * FA_PITCH + cc * 16, vb + go);
            }
            asm volatile("cp.async.commit_group;" ::: "memory");
            asm volatile("cp.async.wait_group 1;" ::: "memory");
        } else {
            asm volatile("cp.async.wait_group 0;" ::: "memory");
        }
        __syncthreads();

        const uint32_t sK = sKV + (uint32_t)(kt & 1) * (2 * FAK_TILE);
        const uint32_t sV = sK + FAK_TILE;
        const int k0 = kt * 64;

        float sacc[8][4];
        #pragma unroll
        for (int nt = 0; nt < 8; nt++)
            #pragma unroll
            for (int q = 0; q < 4; q++) sacc[nt][q] = 0.f;

        #pragma unroll
        for (int ks = 0; ks < 8; ks++) {
            uint32_t aq[4];
            ldsm_x4(aq, sQ + a_off + ks * 32);
            #pragma unroll
            for (int nt = 0; nt < 8; nt++) {
                uint32_t bk[2];
                ldsm_x2(bk, sK + nt * (8 * FA_PITCH) + b_off + ks * 32);
                mma_f32(sacc[nt], aq, bk);
            }
        }

        // causal mask (only when this k tile can cross this warp's rows)
        if (k0 + 63 > q0 + w * 16) {
            #pragma unroll
            for (int nt = 0; nt < 8; nt++) {
                int jg = k0 + nt * 8 + (lane & 3) * 2;
                if (jg > qg0)     sacc[nt][0] = -1e30f;
                if (jg + 1 > qg0) sacc[nt][1] = -1e30f;
                if (jg > qg1)     sacc[nt][2] = -1e30f;
                if (jg + 1 > qg1) sacc[nt][3] = -1e30f;
            }
        }

        float tm0 = -1e30f, tm1 = -1e30f;
        #pragma unroll
        for (int nt = 0; nt < 8; nt++) {
            tm0 = fmaxf(tm0, fmaxf(sacc[nt][0], sacc[nt][1]));
            tm1 = fmaxf(tm1, fmaxf(sacc[nt][2], sacc[nt][3]));
        }
        tm0 = fmaxf(tm0, __shfl_xor_sync(0xffffffffu, tm0, 1));
        tm0 = fmaxf(tm0, __shfl_xor_sync(0xffffffffu, tm0, 2));
        tm1 = fmaxf(tm1, __shfl_xor_sync(0xffffffffu, tm1, 1));
        tm1 = fmaxf(tm1, __shfl_xor_sync(0xffffffffu, tm1, 2));

        float mn0 = fmaxf(m0, tm0), mn1 = fmaxf(m1, tm1);
        float c0 = __expf(m0 - mn0), c1 = __expf(m1 - mn1);
        float ps0 = 0.f, ps1 = 0.f;
        #pragma unroll
        for (int nt = 0; nt < 8; nt++) {
            sacc[nt][0] = __expf(sacc[nt][0] - mn0);
            sacc[nt][1] = __expf(sacc[nt][1] - mn0);
            sacc[nt][2] = __expf(sacc[nt][2] - mn1);
            sacc[nt][3] = __expf(sacc[nt][3] - mn1);
            ps0 += sacc[nt][0] + sacc[nt][1];
            ps1 += sacc[nt][2] + sacc[nt][3];
        }
        ps0 += __shfl_xor_sync(0xffffffffu, ps0, 1);
        ps0 += __shfl_xor_sync(0xffffffffu, ps0, 2);
        ps1 += __shfl_xor_sync(0xffffffffu, ps1, 1);
        ps1 += __shfl_xor_sync(0xffffffffu, ps1, 2);
        l0 = l0 * c0 + ps0;  m0 = mn0;
        l1 = l1 * c1 + ps1;  m1 = mn1;
        #pragma unroll
        for (int nt2 = 0; nt2 < 16; nt2++) {
            oacc[nt2][0] *= c0;  oacc[nt2][1] *= c0;
            oacc[nt2][2] *= c1;  oacc[nt2][3] *= c1;
        }

        uint32_t pa[4][4];
        #pragma unroll
        for (int kp = 0; kp < 4; kp++) {
            pa[kp][0] = pack2h(sacc[2*kp][0],   sacc[2*kp][1]);
            pa[kp][1] = pack2h(sacc[2*kp][2],   sacc[2*kp][3]);
            pa[kp][2] = pack2h(sacc[2*kp+1][0], sacc[2*kp+1][1]);
            pa[kp][3] = pack2h(sacc[2*kp+1][2], sacc[2*kp+1][3]);
        }

        #pragma unroll
        for (int kp = 0; kp < 4; kp++) {
            const uint32_t vb_ = sV + (uint32_t)(kp * 16) * FA_PITCH + v_off;
            #pragma unroll
            for (int nt2 = 0; nt2 < 16; nt2++) {
                uint32_t bv[2];
                ldsm_x2t(bv, vb_ + nt2 * 16);
                mma_f32(oacc[nt2], pa[kp], bv);
            }
        }
        __syncthreads();   // all warps done reading buf[kt&1] before its reuse
    }

    float i0 = 1.f / l0, i1 = 1.f / l1;
    const int b  = bh >> 4;
    const int hh = bh & 15;
    size_t row0 = (size_t)b * LSEQ + qg0;
    size_t row1 = row0 + 8;
    #pragma unroll
    for (int nt2 = 0; nt2 < 16; nt2++) {
        int col = hh * HD + nt2 * 8 + (lane & 3) * 2;
        __half2 h0, h1;
        h0.x = __float2half_rn(oacc[nt2][0] * i0);
        h0.y = __float2half_rn(oacc[nt2][1] * i0);
        h1.x = __float2half_rn(oacc[nt2][2] * i1);
        h1.y = __float2half_rn(oacc[nt2][3] * i1);
        *(__half2*)(O + row0 * DMODEL + col) = h0;
        *(__half2*)(O + row1 * DMODEL + col) = h1;
    }
}

// ---------------------------------------------------------------------------
// Host launcher
// ---------------------------------------------------------------------------
extern "C" void kernel_launch(void* const* d_in, const int* in_sizes, int n_in,
                              void* d_out, int out_size)
{
    const float* x    = (const float*)d_in[0];
    const float* Wqkv = (const float*)d_in[1];
    const float* bqkv = (const float*)d_in[2];
    const float* Wo   = (const float*)d_in[3];
    const float* bo   = (const float*)d_in[4];
    const float* g1   = (const float*)d_in[5];
    const float* g2   = (const float*)d_in[6];
    const float* Wp   = (const float*)d_in[7];
    const float* bp   = (const float*)d_in[8];
    const float* Wff  = (const float*)d_in[9];
    const float* bff  = (const float*)d_in[10];
    float* out = (float*)d_out;

    float *p_x2;
    __half *p_qkvh, *p_xn, *p_o, *p_ff, *p_qf, *p_kf, *p_vf;
    __half *p_wqkv, *p_wo, *p_wp, *p_wff;
    cudaGetSymbolAddress((void**)&p_x2,   g_x2);
    cudaGetSymbolAddress((void**)&p_qkvh, g_qkvh);
    cudaGetSymbolAddress((void**)&p_xn,   g_xn);
    cudaGetSymbolAddress((void**)&p_o,    g_o);
    cudaGetSymbolAddress((void**)&p_ff,   g_ff);
    cudaGetSymbolAddress((void**)&p_qf,   g_qf);
    cudaGetSymbolAddress((void**)&p_kf,   g_kf);
    cudaGetSymbolAddress((void**)&p_vf,   g_vf);
    cudaGetSymbolAddress((void**)&p_wqkv, g_wqkv);
    cudaGetSymbolAddress((void**)&p_wo,   g_wo);
    cudaGetSymbolAddress((void**)&p_wp,   g_wp);
    cudaGetSymbolAddress((void**)&p_wff,  g_wff);

    cudaFuncSetAttribute(attn_mma,        cudaFuncAttributeMaxDynamicSharedMemorySize, FA_SMEM);
    cudaFuncSetAttribute(gemm_kernel<0>,  cudaFuncAttributeMaxDynamicSharedMemorySize, GSMEM);
    cudaFuncSetAttribute(gemm_kernel<1>,  cudaFuncAttributeMaxDynamicSharedMemorySize, GSMEM);
    cudaFuncSetAttribute(gemm_ffn_kernel, cudaFuncAttributeMaxDynamicSharedMemorySize, FGSMEM);

    // Weight transposition (fp16)
    transp_half<<<dim3(3 * DMODEL / 32, DMODEL / 32), 256>>>(Wqkv, p_wqkv, DMODEL, 3 * DMODEL);
    transp_half<<<dim3(DMODEL / 32, DMODEL / 32), 256>>>(Wo, p_wo, DMODEL, DMODEL);
    transp_half<<<dim3(8 * DMODEL / 32, DMODEL / 32), 256>>>(Wp, p_wp, DMODEL, 8 * DMODEL);
    transp_half<<<dim3(DMODEL / 32, 4 * DMODEL / 32), 256>>>(Wff, p_wff, 4 * DMODEL, DMODEL);

    // 1. pre-norm (-> fp16)
    rmsnorm_half<<<ROWS, 256>>>(x, g1, p_xn);

    // 2. QKV projection (fp16 out)
    gemm_kernel<1><<<dim3(3 * DMODEL / 128, ROWS / 128), 512, GSMEM>>>(
        p_xn, p_wqkv, bqkv, nullptr, p_qkvh, DMODEL, 3 * DMODEL);

    // 3. RoPE + split to fp16 Q(scaled)/K/V per-head buffers
    rope_split_kernel<<<(ROWS * NH * 64) / 256, 256>>>(p_qkvh, p_qf, p_kf, p_vf);

    // 4. causal flash attention (fp16 mma, Q-tile 128, pipelined) -> fp16 O
    attn_mma<<<dim3(LSEQ / 128, BD * NH), 256, FA_SMEM>>>(p_qf, p_kf, p_vf, p_o);

    // 5. output projection + residual (fp32 out)
    gemm_kernel<0><<<dim3(DMODEL / 128, ROWS / 128), 512, GSMEM>>>(
        p_o, p_wo, bo, x, p_x2, DMODEL, DMODEL);

    // 6. second pre-norm (-> fp16)
    rmsnorm_half<<<ROWS, 256>>>(p_x2, g2, p_xn);

    // 7+8. FFN up-projection fused with SwiGLU (-> fp16 ff)
    gemm_ffn_kernel<<<dim3(4 * DMODEL / 128, ROWS / 128), 512, FGSMEM>>>(
        p_xn, p_wp, bp, p_ff, DMODEL);

    // 9. FFN down-projection + residual -> output (fp32)
    gemm_kernel<0><<<dim3(DMODEL / 128, ROWS / 128), 512, GSMEM>>>(
        p_ff, p_wff, bff, p_x2, out, 4 * DMODEL, DMODEL);
}